// round 3
// baseline (speedup 1.0000x reference)
#include <cuda_runtime.h>
#include <math.h>

#define FULLMASK 0xffffffffu

constexpr int Bb = 8;
constexpr int Nn = 7168;
constexpr int Uu = 49152;
constexpr int Cc = 64;

// scratch: post-LN1 attention output
__device__ float g_z1[Bb * Nn * Cc];

__device__ __forceinline__ float warp_sum(float v) {
#pragma unroll
    for (int off = 16; off; off >>= 1) v += __shfl_xor_sync(FULLMASK, v, off);
    return v;
}

// ---------------------------------------------------------------------------
// Kernel A: bunch attention (warp per x-token) + LN1 -> g_z1
// ---------------------------------------------------------------------------
template <int TO>
__device__ __forceinline__ void attn_body(
    const float* __restrict__ u, const float* __restrict__ x,
    const float* sWq, const float* sWkT, const float* sWv,
    const float* sbq, const float* sbk, const float* sbv,
    const float* sg1, const float* sbe1,
    float* myLog, int b, int n, int l)
{
    int t, S0, S1;
    if (TO == 4)      { t = n;        S0 = 0;     S1 = 24576; }
    else if (TO == 8) { t = n - 4096; S0 = 8192;  S1 = 32768; }
    else              { t = n - 6144; S0 = 16384; S1 = 40960; }
    int cidx = t * TO;
    int base = (cidx < 8192) ? (S0 + cidx) : (S1 + cidx - 8192);
    const float* uptr = u + ((size_t)b * Uu + base) * Cc;
    const float* xptr = x + ((size_t)b * Nn + n) * Cc;

    float xv0 = xptr[l], xv1 = xptr[l + 32];

    // q[out] = bq + x @ Wq (scale 1/8 folded), 2 accumulators per output to
    // halve the dependent-FMA chain
    float q0a = sbq[l], q1a = sbq[l + 32], q0b = 0.f, q1b = 0.f;
#pragma unroll
    for (int in = 0; in < 32; in++) {
        float xb = __shfl_sync(FULLMASK, xv0, in);
        if (in & 1) { q0b += xb * sWq[in * 64 + l]; q1b += xb * sWq[in * 64 + l + 32]; }
        else        { q0a += xb * sWq[in * 64 + l]; q1a += xb * sWq[in * 64 + l + 32]; }
    }
#pragma unroll
    for (int in = 0; in < 32; in++) {
        float xb = __shfl_sync(FULLMASK, xv1, in);
        if (in & 1) { q0b += xb * sWq[(in + 32) * 64 + l]; q1b += xb * sWq[(in + 32) * 64 + l + 32]; }
        else        { q0a += xb * sWq[(in + 32) * 64 + l]; q1a += xb * sWq[(in + 32) * 64 + l + 32]; }
    }
    float q0 = (q0a + q0b) * 0.125f;
    float q1 = (q1a + q1b) * 0.125f;

    // w[g][in] = sum_{oc in group g} Wk[in][oc] * q[oc]   (and bk·q per group)
    float w0[4] = {0.f, 0.f, 0.f, 0.f}, w1[4] = {0.f, 0.f, 0.f, 0.f};
    float bkq[4] = {0.f, 0.f, 0.f, 0.f};
#pragma unroll
    for (int oc = 0; oc < 32; oc++) {
        float qb = __shfl_sync(FULLMASK, q0, oc);
        const int g = oc >> 4;
        w0[g] += qb * sWkT[oc * 65 + l];
        w1[g] += qb * sWkT[oc * 65 + l + 32];
        bkq[g] += qb * sbk[oc];
    }
#pragma unroll
    for (int oc = 32; oc < 64; oc++) {
        float qb = __shfl_sync(FULLMASK, q1, oc - 32);
        const int g = oc >> 4;
        w0[g] += qb * sWkT[oc * 65 + l];
        w1[g] += qb * sWkT[oc * 65 + l + 32];
        bkq[g] += qb * sbk[oc];
    }

    // load the TO contiguous u rows into registers
    float ur0[TO], ur1[TO];
#pragma unroll
    for (int r = 0; r < TO; r++) {
        ur0[r] = uptr[r * 64 + l];
        ur1[r] = uptr[r * 64 + l + 32];
    }

    // logits
#pragma unroll
    for (int r = 0; r < TO; r++) {
        float p0 = ur0[r] * w0[0] + ur1[r] * w1[0];
        float p1 = ur0[r] * w0[1] + ur1[r] * w1[1];
        float p2 = ur0[r] * w0[2] + ur1[r] * w1[2];
        float p3 = ur0[r] * w0[3] + ur1[r] * w1[3];
#pragma unroll
        for (int off = 16; off; off >>= 1) {
            p0 += __shfl_xor_sync(FULLMASK, p0, off);
            p1 += __shfl_xor_sync(FULLMASK, p1, off);
            p2 += __shfl_xor_sync(FULLMASK, p2, off);
            p3 += __shfl_xor_sync(FULLMASK, p3, off);
        }
        if (l == 0) {
            myLog[r * 4 + 0] = p0 + bkq[0];
            myLog[r * 4 + 1] = p1 + bkq[1];
            myLog[r * 4 + 2] = p2 + bkq[2];
            myLog[r * 4 + 3] = p3 + bkq[3];
        }
    }
    __syncwarp();

    // softmax over r, one group per lane (lanes 0..3)
    if (l < 4) {
        float m = -1e30f;
#pragma unroll
        for (int r = 0; r < TO; r++) m = fmaxf(m, myLog[r * 4 + l]);
        float s = 0.f;
#pragma unroll
        for (int r = 0; r < TO; r++) {
            float e = __expf(myLog[r * 4 + l] - m);
            s += e;
            myLog[r * 4 + l] = e;
        }
        float inv = 1.f / s;
#pragma unroll
        for (int r = 0; r < TO; r++) myLog[r * 4 + l] *= inv;
    }
    __syncwarp();

    // ubar[g] = sum_r p[r][g] * u_r
    float ub0[4] = {0.f, 0.f, 0.f, 0.f}, ub1[4] = {0.f, 0.f, 0.f, 0.f};
#pragma unroll
    for (int r = 0; r < TO; r++) {
        float pg0 = myLog[r * 4 + 0], pg1 = myLog[r * 4 + 1];
        float pg2 = myLog[r * 4 + 2], pg3 = myLog[r * 4 + 3];
        ub0[0] += pg0 * ur0[r]; ub1[0] += pg0 * ur1[r];
        ub0[1] += pg1 * ur0[r]; ub1[1] += pg1 * ur1[r];
        ub0[2] += pg2 * ur0[r]; ub1[2] += pg2 * ur1[r];
        ub0[3] += pg3 * ur0[r]; ub1[3] += pg3 * ur1[r];
    }

    // attv[oc] = ubar[oc/16] @ Wv[:,oc] + bv[oc]; 2 accumulators per output
    float av0a = sbv[l], av1a = sbv[l + 32], av0b = 0.f, av1b = 0.f;
    const bool hi = (l & 16);
#pragma unroll
    for (int in = 0; in < 32; in++) {
        float a0 = __shfl_sync(FULLMASK, ub0[0], in);
        float a1 = __shfl_sync(FULLMASK, ub0[1], in);
        float a2 = __shfl_sync(FULLMASK, ub0[2], in);
        float a3 = __shfl_sync(FULLMASK, ub0[3], in);
        if (in & 1) {
            av0b += (hi ? a1 : a0) * sWv[in * 64 + l];
            av1b += (hi ? a3 : a2) * sWv[in * 64 + l + 32];
        } else {
            av0a += (hi ? a1 : a0) * sWv[in * 64 + l];
            av1a += (hi ? a3 : a2) * sWv[in * 64 + l + 32];
        }
    }
#pragma unroll
    for (int in = 0; in < 32; in++) {
        float a0 = __shfl_sync(FULLMASK, ub1[0], in);
        float a1 = __shfl_sync(FULLMASK, ub1[1], in);
        float a2 = __shfl_sync(FULLMASK, ub1[2], in);
        float a3 = __shfl_sync(FULLMASK, ub1[3], in);
        if (in & 1) {
            av0b += (hi ? a1 : a0) * sWv[(in + 32) * 64 + l];
            av1b += (hi ? a3 : a2) * sWv[(in + 32) * 64 + l + 32];
        } else {
            av0a += (hi ? a1 : a0) * sWv[(in + 32) * 64 + l];
            av1a += (hi ? a3 : a2) * sWv[(in + 32) * 64 + l + 32];
        }
    }
    float av0 = av0a + av0b, av1 = av1a + av1b;

    // LN1 and write to scratch
    float mean = warp_sum(av0 + av1) * (1.f / 64.f);
    float d0 = av0 - mean, d1 = av1 - mean;
    float var = warp_sum(d0 * d0 + d1 * d1) * (1.f / 64.f);
    float inv = rsqrtf(var + 1e-5f);
    size_t o = ((size_t)b * Nn + n) * Cc;
    g_z1[o + l]      = d0 * inv * sg1[l]      + sbe1[l];
    g_z1[o + l + 32] = d1 * inv * sg1[l + 32] + sbe1[l + 32];
}

extern "C" __global__ void __launch_bounds__(256)
kernelA(const float* __restrict__ u, const float* __restrict__ x,
        const float* __restrict__ Wk, const float* __restrict__ bk,
        const float* __restrict__ Wq, const float* __restrict__ bq,
        const float* __restrict__ Wv, const float* __restrict__ bv,
        const float* __restrict__ g1, const float* __restrict__ be1)
{
    extern __shared__ float sm[];
    float* sWq  = sm;                 // 4096
    float* sWkT = sm + 4096;          // 64*65 = 4160 (pitch 65, conflict-free)
    float* sWv  = sm + 4096 + 4160;   // 4096
    float* sbq  = sWv + 4096;         // 64
    float* sbk  = sbq + 64;
    float* sbv  = sbk + 64;
    float* sg1  = sbv + 64;
    float* sbe1 = sg1 + 64;
    float* sLog = sbe1 + 64;          // 8 warps * 64

    int tid = threadIdx.x;
    for (int i = tid; i < 4096; i += 256) {
        sWq[i] = Wq[i];
        sWv[i] = Wv[i];
        int in = i >> 6, oc = i & 63;
        sWkT[oc * 65 + in] = Wk[i];
    }
    if (tid < 64) {
        sbq[tid] = bq[tid]; sbk[tid] = bk[tid]; sbv[tid] = bv[tid];
        sg1[tid] = g1[tid]; sbe1[tid] = be1[tid];
    }
    __syncthreads();

    int warp = tid >> 5, l = tid & 31;
    float* myLog = sLog + warp * 64;

    for (int blk = blockIdx.x; blk < (Bb * Nn / 8); blk += gridDim.x) {
        int token = blk * 8 + warp;
        int b = token / Nn, n = token % Nn;
        int n0 = (blk % (Nn / 8)) * 8;
        if (n0 < 4096)
            attn_body<4>(u, x, sWq, sWkT, sWv, sbq, sbk, sbv, sg1, sbe1, myLog, b, n, l);
        else if (n0 < 6144)
            attn_body<8>(u, x, sWq, sWkT, sWv, sbq, sbk, sbv, sg1, sbe1, myLog, b, n, l);
        else
            attn_body<16>(u, x, sWq, sWkT, sWv, sbq, sbk, sbv, sg1, sbe1, myLog, b, n, l);
    }
}

// ---------------------------------------------------------------------------
// Kernel B: MLP (64->256 gelu ->64) + LN2 + shortcut (x@Ws+bs)
// 512 threads, 32-token tiles: 16 warps/SM instead of 8.
// ---------------------------------------------------------------------------
extern "C" __global__ void __launch_bounds__(512)
kernelB(const float* __restrict__ x,
        const float* __restrict__ Wm1, const float* __restrict__ bm1,
        const float* __restrict__ Wm2, const float* __restrict__ bm2,
        const float* __restrict__ g2,  const float* __restrict__ be2,
        const float* __restrict__ Ws,  const float* __restrict__ bs,
        float* __restrict__ out)
{
    extern __shared__ float sm[];
    float* sWm1 = sm;               // 16384
    float* sWm2 = sm + 16384;       // 16384
    float* sWs  = sm + 32768;       // 4096
    float* sbm1 = sm + 36864;       // 256
    float* sbm2 = sbm1 + 256;       // 64
    float* sg2  = sbm2 + 64;
    float* sbe2 = sg2 + 64;
    float* sbs  = sbe2 + 64;
    float* sZ   = sbs + 64;         // 32*64
    float* sX   = sZ + 2048;        // 32*64
    float* sH   = sX + 2048;        // 32*256

    int tid = threadIdx.x;
    for (int i = tid; i < 16384; i += 512) { sWm1[i] = Wm1[i]; sWm2[i] = Wm2[i]; }
    for (int i = tid; i < 4096; i += 512) sWs[i] = Ws[i];
    if (tid < 256) sbm1[tid] = bm1[tid];
    if (tid < 64) { sbm2[tid] = bm2[tid]; sg2[tid] = g2[tid]; sbe2[tid] = be2[tid]; sbs[tid] = bs[tid]; }
    __syncthreads();

    int warp = tid >> 5, l = tid & 31;
    int jb = tid & 63, tg = tid >> 6;   // 8 token-groups of 4 tokens, 64 hidden-cols each
    const int NTILES = Bb * Nn / 32;    // 1792

    for (int tile = blockIdx.x; tile < NTILES; tile += gridDim.x) {
        size_t base = (size_t)tile * 32 * 64;
        for (int i = tid; i < 2048; i += 512) {
            sZ[i] = g_z1[base + i];
            sX[i] = x[base + i];
        }
        __syncthreads();

        // MLP1: h[t][j] = gelu(z_t @ Wm1 + bm1); 4 tokens x 4 cols per thread
        float h[4][4];
#pragma unroll
        for (int tt = 0; tt < 4; tt++)
#pragma unroll
            for (int k = 0; k < 4; k++) h[tt][k] = sbm1[jb + 64 * k];

#pragma unroll 8
        for (int c = 0; c < 64; c++) {
            float zr[4];
#pragma unroll
            for (int tt = 0; tt < 4; tt++) zr[tt] = sZ[(tg * 4 + tt) * 64 + c];
            float wr[4];
#pragma unroll
            for (int k = 0; k < 4; k++) wr[k] = sWm1[c * 256 + jb + 64 * k];
#pragma unroll
            for (int tt = 0; tt < 4; tt++)
#pragma unroll
                for (int k = 0; k < 4; k++) h[tt][k] += zr[tt] * wr[k];
        }
#pragma unroll
        for (int tt = 0; tt < 4; tt++)
#pragma unroll
            for (int k = 0; k < 4; k++) {
                float v = h[tt][k];
                h[tt][k] = v * 0.5f * (1.f + erff(v * 0.70710678118654752f));
                sH[(tg * 4 + tt) * 256 + jb + 64 * k] = h[tt][k];
            }
        __syncthreads();

        // MLP2 + shortcut; warp handles 2 tokens, lane -> channels l, l+32
        float o[2][2], sc[2][2];
#pragma unroll
        for (int tt = 0; tt < 2; tt++) {
            o[tt][0] = sbm2[l];  o[tt][1] = sbm2[l + 32];
            sc[tt][0] = sbs[l];  sc[tt][1] = sbs[l + 32];
        }
#pragma unroll 8
        for (int j = 0; j < 256; j++) {
            float w2a = sWm2[j * 64 + l], w2b = sWm2[j * 64 + l + 32];
#pragma unroll
            for (int tt = 0; tt < 2; tt++) {
                float hb = sH[(warp * 2 + tt) * 256 + j];
                o[tt][0] += hb * w2a;
                o[tt][1] += hb * w2b;
            }
        }
#pragma unroll 8
        for (int in = 0; in < 64; in++) {
            float wsa = sWs[in * 64 + l], wsb = sWs[in * 64 + l + 32];
#pragma unroll
            for (int tt = 0; tt < 2; tt++) {
                float xb = sX[(warp * 2 + tt) * 64 + in];
                sc[tt][0] += xb * wsa;
                sc[tt][1] += xb * wsb;
            }
        }
#pragma unroll
        for (int tt = 0; tt < 2; tt++) {
            float mean = warp_sum(o[tt][0] + o[tt][1]) * (1.f / 64.f);
            float d0 = o[tt][0] - mean, d1 = o[tt][1] - mean;
            float var = warp_sum(d0 * d0 + d1 * d1) * (1.f / 64.f);
            float inv = rsqrtf(var + 1e-5f);
            size_t oo = base + (size_t)(warp * 2 + tt) * 64;
            out[oo + l]      = d0 * inv * sg2[l]      + sbe2[l]      + sc[tt][0];
            out[oo + l + 32] = d1 * inv * sg2[l + 32] + sbe2[l + 32] + sc[tt][1];
        }
        __syncthreads();
    }
}

// ---------------------------------------------------------------------------
extern "C" void kernel_launch(void* const* d_in, const int* in_sizes, int n_in,
                              void* d_out, int out_size)
{
    const float* u   = (const float*)d_in[0];
    const float* x   = (const float*)d_in[1];
    const float* Wk  = (const float*)d_in[2];
    const float* bk  = (const float*)d_in[3];
    const float* Wq  = (const float*)d_in[4];
    const float* bq  = (const float*)d_in[5];
    const float* Wv  = (const float*)d_in[6];
    const float* bv  = (const float*)d_in[7];
    const float* g1  = (const float*)d_in[8];
    const float* be1 = (const float*)d_in[9];
    const float* Wm1 = (const float*)d_in[10];
    const float* bm1 = (const float*)d_in[11];
    const float* Wm2 = (const float*)d_in[12];
    const float* bm2 = (const float*)d_in[13];
    const float* g2  = (const float*)d_in[14];
    const float* be2 = (const float*)d_in[15];
    const float* Ws  = (const float*)d_in[16];
    const float* bs  = (const float*)d_in[17];
    float* out = (float*)d_out;

    const int smemA = (4096 + 4160 + 4096 + 5 * 64 + 8 * 64) * 4;   // 52800 B
    const int smemB = (16384 + 16384 + 4096 + 256 + 4 * 64 + 2048 + 2048 + 8192) * 4; // 198656 B

    cudaFuncSetAttribute(kernelA, cudaFuncAttributeMaxDynamicSharedMemorySize, smemA);
    cudaFuncSetAttribute(kernelB, cudaFuncAttributeMaxDynamicSharedMemorySize, smemB);

    kernelA<<<592, 256, smemA>>>(u, x, Wk, bk, Wq, bq, Wv, bv, g1, be1);
    kernelB<<<148, 512, smemB>>>(x, Wm1, bm1, Wm2, bm2, g2, be2, Ws, bs, out);
}

// round 4
// speedup vs baseline: 1.1595x; 1.1595x over previous
#include <cuda_runtime.h>
#include <math.h>

#define FULLMASK 0xffffffffu

constexpr int Bb = 8;
constexpr int Nn = 7168;
constexpr int Uu = 49152;
constexpr int Cc = 64;

// scratch: post-LN1 attention output
__device__ float g_z1[Bb * Nn * Cc];

__device__ __forceinline__ float warp_sum(float v) {
#pragma unroll
    for (int off = 16; off; off >>= 1) v += __shfl_xor_sync(FULLMASK, v, off);
    return v;
}

__device__ __forceinline__ float dot4(float4 a, float4 b, float acc) {
    acc = fmaf(a.x, b.x, acc);
    acc = fmaf(a.y, b.y, acc);
    acc = fmaf(a.z, b.z, acc);
    acc = fmaf(a.w, b.w, acc);
    return acc;
}

// ---------------------------------------------------------------------------
// Kernel A: bunch attention (warp per x-token) + LN1 -> g_z1
// ---------------------------------------------------------------------------
template <int TO>
__device__ __forceinline__ void attn_body(
    const float* __restrict__ u, const float* __restrict__ x,
    const float* sWq, const float* sWkT, const float* sWvT,
    const float* sbq, const float* sbk, const float* sbv,
    const float* sg1, const float* sbe1,
    float* myLog, float* myUb, int b, int n, int l)
{
    int t, S0, S1;
    if (TO == 4)      { t = n;        S0 = 0;     S1 = 24576; }
    else if (TO == 8) { t = n - 4096; S0 = 8192;  S1 = 32768; }
    else              { t = n - 6144; S0 = 16384; S1 = 40960; }
    int cidx = t * TO;
    int base = (cidx < 8192) ? (S0 + cidx) : (S1 + cidx - 8192);
    const float* uptr = u + ((size_t)b * Uu + base) * Cc;
    const float* xptr = x + ((size_t)b * Nn + n) * Cc;

    float xv0 = xptr[l], xv1 = xptr[l + 32];

    // q[out] = bq + x @ Wq (scale 1/8 folded), 2 accumulators per output
    float q0a = sbq[l], q1a = sbq[l + 32], q0b = 0.f, q1b = 0.f;
#pragma unroll
    for (int in = 0; in < 32; in++) {
        float xb = __shfl_sync(FULLMASK, xv0, in);
        if (in & 1) { q0b += xb * sWq[in * 64 + l]; q1b += xb * sWq[in * 64 + l + 32]; }
        else        { q0a += xb * sWq[in * 64 + l]; q1a += xb * sWq[in * 64 + l + 32]; }
    }
#pragma unroll
    for (int in = 0; in < 32; in++) {
        float xb = __shfl_sync(FULLMASK, xv1, in);
        if (in & 1) { q0b += xb * sWq[(in + 32) * 64 + l]; q1b += xb * sWq[(in + 32) * 64 + l + 32]; }
        else        { q0a += xb * sWq[(in + 32) * 64 + l]; q1a += xb * sWq[(in + 32) * 64 + l + 32]; }
    }
    float q0 = (q0a + q0b) * 0.125f;
    float q1 = (q1a + q1b) * 0.125f;

    // w[g][in] = sum_{oc in group g} Wk[in][oc] * q[oc]   (and bk·q per group)
    float w0[4] = {0.f, 0.f, 0.f, 0.f}, w1[4] = {0.f, 0.f, 0.f, 0.f};
    float bkq[4] = {0.f, 0.f, 0.f, 0.f};
#pragma unroll
    for (int oc = 0; oc < 32; oc++) {
        float qb = __shfl_sync(FULLMASK, q0, oc);
        const int g = oc >> 4;
        w0[g] += qb * sWkT[oc * 65 + l];
        w1[g] += qb * sWkT[oc * 65 + l + 32];
        bkq[g] += qb * sbk[oc];
    }
#pragma unroll
    for (int oc = 32; oc < 64; oc++) {
        float qb = __shfl_sync(FULLMASK, q1, oc - 32);
        const int g = oc >> 4;
        w0[g] += qb * sWkT[oc * 65 + l];
        w1[g] += qb * sWkT[oc * 65 + l + 32];
        bkq[g] += qb * sbk[oc];
    }

    // load the TO contiguous u rows into registers
    float ur0[TO], ur1[TO];
#pragma unroll
    for (int r = 0; r < TO; r++) {
        ur0[r] = uptr[r * 64 + l];
        ur1[r] = uptr[r * 64 + l + 32];
    }

    // logits
#pragma unroll
    for (int r = 0; r < TO; r++) {
        float p0 = ur0[r] * w0[0] + ur1[r] * w1[0];
        float p1 = ur0[r] * w0[1] + ur1[r] * w1[1];
        float p2 = ur0[r] * w0[2] + ur1[r] * w1[2];
        float p3 = ur0[r] * w0[3] + ur1[r] * w1[3];
#pragma unroll
        for (int off = 16; off; off >>= 1) {
            p0 += __shfl_xor_sync(FULLMASK, p0, off);
            p1 += __shfl_xor_sync(FULLMASK, p1, off);
            p2 += __shfl_xor_sync(FULLMASK, p2, off);
            p3 += __shfl_xor_sync(FULLMASK, p3, off);
        }
        if (l == 0) {
            myLog[r * 4 + 0] = p0 + bkq[0];
            myLog[r * 4 + 1] = p1 + bkq[1];
            myLog[r * 4 + 2] = p2 + bkq[2];
            myLog[r * 4 + 3] = p3 + bkq[3];
        }
    }
    __syncwarp();

    // softmax over r, one group per lane (lanes 0..3)
    if (l < 4) {
        float m = -1e30f;
#pragma unroll
        for (int r = 0; r < TO; r++) m = fmaxf(m, myLog[r * 4 + l]);
        float s = 0.f;
#pragma unroll
        for (int r = 0; r < TO; r++) {
            float e = __expf(myLog[r * 4 + l] - m);
            s += e;
            myLog[r * 4 + l] = e;
        }
        float inv = 1.f / s;
#pragma unroll
        for (int r = 0; r < TO; r++) myLog[r * 4 + l] *= inv;
    }
    __syncwarp();

    // ubar[g] = sum_r p[r][g] * u_r   (per-channel in each lane)
    float ub0[4] = {0.f, 0.f, 0.f, 0.f}, ub1[4] = {0.f, 0.f, 0.f, 0.f};
#pragma unroll
    for (int r = 0; r < TO; r++) {
        float pg0 = myLog[r * 4 + 0], pg1 = myLog[r * 4 + 1];
        float pg2 = myLog[r * 4 + 2], pg3 = myLog[r * 4 + 3];
        ub0[0] += pg0 * ur0[r]; ub1[0] += pg0 * ur1[r];
        ub0[1] += pg1 * ur0[r]; ub1[1] += pg1 * ur1[r];
        ub0[2] += pg2 * ur0[r]; ub1[2] += pg2 * ur1[r];
        ub0[3] += pg3 * ur0[r]; ub1[3] += pg3 * ur1[r];
    }

    // stage ubar to per-warp smem (pitch 68, conflict-free), then v-proj via
    // float4 reads instead of 256 shuffles
    __syncwarp();
#pragma unroll
    for (int g = 0; g < 4; g++) {
        myUb[g * 68 + l]      = ub0[g];
        myUb[g * 68 + 32 + l] = ub1[g];
    }
    __syncwarp();

    const int ga = l >> 4;      // group owning channel l       (0 or 1)
    const int gb = ga + 2;      // group owning channel l + 32  (2 or 3)
    float av0 = sbv[l], av1 = sbv[l + 32];
#pragma unroll
    for (int in = 0; in < 64; in += 4) {
        float4 ua = *(const float4*)&myUb[ga * 68 + in];
        float4 ub = *(const float4*)&myUb[gb * 68 + in];
        float4 wa = *(const float4*)&sWvT[l * 68 + in];
        float4 wb = *(const float4*)&sWvT[(l + 32) * 68 + in];
        av0 = dot4(ua, wa, av0);
        av1 = dot4(ub, wb, av1);
    }

    // LN1 and write to scratch
    float mean = warp_sum(av0 + av1) * (1.f / 64.f);
    float d0 = av0 - mean, d1 = av1 - mean;
    float var = warp_sum(d0 * d0 + d1 * d1) * (1.f / 64.f);
    float inv = rsqrtf(var + 1e-5f);
    size_t o = ((size_t)b * Nn + n) * Cc;
    g_z1[o + l]      = d0 * inv * sg1[l]      + sbe1[l];
    g_z1[o + l + 32] = d1 * inv * sg1[l + 32] + sbe1[l + 32];
}

extern "C" __global__ void __launch_bounds__(256)
kernelA(const float* __restrict__ u, const float* __restrict__ x,
        const float* __restrict__ Wk, const float* __restrict__ bk,
        const float* __restrict__ Wq, const float* __restrict__ bq,
        const float* __restrict__ Wv, const float* __restrict__ bv,
        const float* __restrict__ g1, const float* __restrict__ be1)
{
    extern __shared__ float sm[];
    float* sWq  = sm;                 // 4096
    float* sWkT = sm + 4096;          // 64*65 = 4160 (pitch 65, conflict-free)
    float* sWvT = sm + 4096 + 4160;   // 64*68 = 4352 (transposed, pitch 68)
    float* sbq  = sWvT + 4352;        // 64
    float* sbk  = sbq + 64;
    float* sbv  = sbk + 64;
    float* sg1  = sbv + 64;
    float* sbe1 = sg1 + 64;
    float* sLog = sbe1 + 64;          // 8 warps * 64
    float* sUb  = sLog + 512;         // 8 warps * 4*68 = 2176

    int tid = threadIdx.x;
    for (int i = tid; i < 4096; i += 256) {
        sWq[i] = Wq[i];
        int in = i >> 6, oc = i & 63;
        sWkT[oc * 65 + in] = Wk[i];
        sWvT[oc * 68 + in] = Wv[i];
    }
    if (tid < 64) {
        sbq[tid] = bq[tid]; sbk[tid] = bk[tid]; sbv[tid] = bv[tid];
        sg1[tid] = g1[tid]; sbe1[tid] = be1[tid];
    }
    __syncthreads();

    int warp = tid >> 5, l = tid & 31;
    float* myLog = sLog + warp * 64;
    float* myUb  = sUb + warp * 272;

    for (int blk = blockIdx.x; blk < (Bb * Nn / 8); blk += gridDim.x) {
        int token = blk * 8 + warp;
        int b = token / Nn, n = token % Nn;
        int n0 = (blk % (Nn / 8)) * 8;
        if (n0 < 4096)
            attn_body<4>(u, x, sWq, sWkT, sWvT, sbq, sbk, sbv, sg1, sbe1, myLog, myUb, b, n, l);
        else if (n0 < 6144)
            attn_body<8>(u, x, sWq, sWkT, sWvT, sbq, sbk, sbv, sg1, sbe1, myLog, myUb, b, n, l);
        else
            attn_body<16>(u, x, sWq, sWkT, sWvT, sbq, sbk, sbv, sg1, sbe1, myLog, myUb, b, n, l);
    }
}

// ---------------------------------------------------------------------------
// Kernel B: MLP (64->256 gelu ->64) + LN2 + shortcut (x@Ws+bs)
// 512 threads, 32-token tiles, float4 smem traffic throughout.
// ---------------------------------------------------------------------------
extern "C" __global__ void __launch_bounds__(512)
kernelB(const float* __restrict__ x,
        const float* __restrict__ Wm1, const float* __restrict__ bm1,
        const float* __restrict__ Wm2, const float* __restrict__ bm2,
        const float* __restrict__ g2,  const float* __restrict__ be2,
        const float* __restrict__ Ws,  const float* __restrict__ bs,
        float* __restrict__ out)
{
    extern __shared__ float sm[];
    float* sWm1  = sm;                 // 16384 (row-major [64][256])
    float* sWm2T = sm + 16384;         // 64 * 260 = 16640 (transposed, pitch 260)
    float* sWsT  = sWm2T + 16640;      // 64 * 68 = 4352  (transposed, pitch 68)
    float* sbm1  = sWsT + 4352;        // 256
    float* sbm2  = sbm1 + 256;         // 64
    float* sg2   = sbm2 + 64;
    float* sbe2  = sg2 + 64;
    float* sbs   = sbe2 + 64;
    float* sZ    = sbs + 64;           // 32*64
    float* sX    = sZ + 2048;          // 32*64
    float* sH    = sX + 2048;          // 32*256

    int tid = threadIdx.x;
    for (int i = tid; i < 16384; i += 512) {
        sWm1[i] = Wm1[i];
        int j = i >> 6, oc = i & 63;           // Wm2[j][oc]
        sWm2T[oc * 260 + j] = Wm2[i];
    }
    for (int i = tid; i < 4096; i += 512) {
        int in = i >> 6, oc = i & 63;          // Ws[in][oc]
        sWsT[oc * 68 + in] = Ws[i];
    }
    if (tid < 256) sbm1[tid] = bm1[tid];
    if (tid < 64) { sbm2[tid] = bm2[tid]; sg2[tid] = g2[tid]; sbe2[tid] = be2[tid]; sbs[tid] = bs[tid]; }
    __syncthreads();

    int warp = tid >> 5, l = tid & 31;
    int j4 = (tid & 63) * 4;            // 4 contiguous hidden cols
    int tg = tid >> 6;                  // 8 token-groups of 4 tokens
    const int NTILES = Bb * Nn / 32;    // 1792

    for (int tile = blockIdx.x; tile < NTILES; tile += gridDim.x) {
        size_t base = (size_t)tile * 32 * 64;
        // 2048 floats each = one float4 per thread
        ((float4*)sZ)[tid] = ((const float4*)(g_z1 + base))[tid];
        ((float4*)sX)[tid] = ((const float4*)(x + base))[tid];
        __syncthreads();

        // MLP1: h[t][jj] = gelu(z_t @ Wm1 + bm1); 4 tokens x 4 contiguous cols
        float h[4][4];
#pragma unroll
        for (int tt = 0; tt < 4; tt++)
#pragma unroll
            for (int kk = 0; kk < 4; kk++) h[tt][kk] = sbm1[j4 + kk];

#pragma unroll 4
        for (int c = 0; c < 64; c += 4) {
            float wr[16];
#pragma unroll
            for (int cc = 0; cc < 4; cc++) {
                float4 w4 = *(const float4*)&sWm1[(c + cc) * 256 + j4];
                wr[cc * 4 + 0] = w4.x; wr[cc * 4 + 1] = w4.y;
                wr[cc * 4 + 2] = w4.z; wr[cc * 4 + 3] = w4.w;
            }
#pragma unroll
            for (int tt = 0; tt < 4; tt++) {
                float4 z4 = *(const float4*)&sZ[(tg * 4 + tt) * 64 + c];
                float zf[4] = {z4.x, z4.y, z4.z, z4.w};
#pragma unroll
                for (int cc = 0; cc < 4; cc++)
#pragma unroll
                    for (int kk = 0; kk < 4; kk++)
                        h[tt][kk] = fmaf(zf[cc], wr[cc * 4 + kk], h[tt][kk]);
            }
        }
#pragma unroll
        for (int tt = 0; tt < 4; tt++) {
            float4 g4;
            float* gp = (float*)&g4;
#pragma unroll
            for (int kk = 0; kk < 4; kk++) {
                float v = h[tt][kk];
                gp[kk] = v * 0.5f * (1.f + erff(v * 0.70710678118654752f));
            }
            *(float4*)&sH[(tg * 4 + tt) * 256 + j4] = g4;
        }
        __syncthreads();

        // MLP2 + shortcut; warp handles 2 tokens, lane -> channels l, l+32
        float o[2][2], sc[2][2];
#pragma unroll
        for (int tt = 0; tt < 2; tt++) {
            o[tt][0] = sbm2[l];  o[tt][1] = sbm2[l + 32];
            sc[tt][0] = sbs[l];  sc[tt][1] = sbs[l + 32];
        }
#pragma unroll 4
        for (int j = 0; j < 256; j += 4) {
            float4 wa = *(const float4*)&sWm2T[l * 260 + j];
            float4 wb = *(const float4*)&sWm2T[(l + 32) * 260 + j];
#pragma unroll
            for (int tt = 0; tt < 2; tt++) {
                float4 hb = *(const float4*)&sH[(warp * 2 + tt) * 256 + j];
                o[tt][0] = dot4(hb, wa, o[tt][0]);
                o[tt][1] = dot4(hb, wb, o[tt][1]);
            }
        }
#pragma unroll 4
        for (int in = 0; in < 64; in += 4) {
            float4 wa = *(const float4*)&sWsT[l * 68 + in];
            float4 wb = *(const float4*)&sWsT[(l + 32) * 68 + in];
#pragma unroll
            for (int tt = 0; tt < 2; tt++) {
                float4 x4 = *(const float4*)&sX[(warp * 2 + tt) * 64 + in];
                sc[tt][0] = dot4(x4, wa, sc[tt][0]);
                sc[tt][1] = dot4(x4, wb, sc[tt][1]);
            }
        }
#pragma unroll
        for (int tt = 0; tt < 2; tt++) {
            float mean = warp_sum(o[tt][0] + o[tt][1]) * (1.f / 64.f);
            float d0 = o[tt][0] - mean, d1 = o[tt][1] - mean;
            float var = warp_sum(d0 * d0 + d1 * d1) * (1.f / 64.f);
            float inv = rsqrtf(var + 1e-5f);
            size_t oo = base + (size_t)(warp * 2 + tt) * 64;
            out[oo + l]      = d0 * inv * sg2[l]      + sbe2[l]      + sc[tt][0];
            out[oo + l + 32] = d1 * inv * sg2[l + 32] + sbe2[l + 32] + sc[tt][1];
        }
        __syncthreads();
    }
}

// ---------------------------------------------------------------------------
extern "C" void kernel_launch(void* const* d_in, const int* in_sizes, int n_in,
                              void* d_out, int out_size)
{
    const float* u   = (const float*)d_in[0];
    const float* x   = (const float*)d_in[1];
    const float* Wk  = (const float*)d_in[2];
    const float* bk  = (const float*)d_in[3];
    const float* Wq  = (const float*)d_in[4];
    const float* bq  = (const float*)d_in[5];
    const float* Wv  = (const float*)d_in[6];
    const float* bv  = (const float*)d_in[7];
    const float* g1  = (const float*)d_in[8];
    const float* be1 = (const float*)d_in[9];
    const float* Wm1 = (const float*)d_in[10];
    const float* bm1 = (const float*)d_in[11];
    const float* Wm2 = (const float*)d_in[12];
    const float* bm2 = (const float*)d_in[13];
    const float* g2  = (const float*)d_in[14];
    const float* be2 = (const float*)d_in[15];
    const float* Ws  = (const float*)d_in[16];
    const float* bs  = (const float*)d_in[17];
    float* out = (float*)d_out;

    const int smemA = (4096 + 4160 + 4352 + 5 * 64 + 512 + 2176) * 4;          // 62464 B
    const int smemB = (16384 + 16640 + 4352 + 256 + 4 * 64 + 2048 + 2048 + 8192) * 4; // 200704 B

    cudaFuncSetAttribute(kernelA, cudaFuncAttributeMaxDynamicSharedMemorySize, smemA);
    cudaFuncSetAttribute(kernelB, cudaFuncAttributeMaxDynamicSharedMemorySize, smemB);

    kernelA<<<444, 256, smemA>>>(u, x, Wk, bk, Wq, bq, Wv, bv, g1, be1);
    kernelB<<<148, 512, smemB>>>(x, Wm1, bm1, Wm2, bm2, g2, be2, Ws, bs, out);
}

// round 5
// speedup vs baseline: 1.5461x; 1.3334x over previous
#include <cuda_runtime.h>
#include <math.h>
#include <stdint.h>

#define FULLMASK 0xffffffffu

constexpr int Bb = 8;
constexpr int Nn = 7168;
constexpr int Uu = 49152;
constexpr int Cc = 64;

// scratch: post-LN1 attention output
__device__ float g_z1[Bb * Nn * Cc];

__device__ __forceinline__ float warp_sum(float v) {
#pragma unroll
    for (int off = 16; off; off >>= 1) v += __shfl_xor_sync(FULLMASK, v, off);
    return v;
}

__device__ __forceinline__ float dot4(float4 a, float4 b, float acc) {
    acc = fmaf(a.x, b.x, acc);
    acc = fmaf(a.y, b.y, acc);
    acc = fmaf(a.z, b.z, acc);
    acc = fmaf(a.w, b.w, acc);
    return acc;
}

__device__ __forceinline__ float to_tf32(float x) {
    uint32_t r;
    asm("cvt.rna.tf32.f32 %0, %1;" : "=r"(r) : "f"(x));
    return __uint_as_float(r);
}

__device__ __forceinline__ void mma_tf32(float c[4],
    uint32_t a0, uint32_t a1, uint32_t a2, uint32_t a3,
    uint32_t b0, uint32_t b1)
{
    asm volatile(
        "mma.sync.aligned.m16n8k8.row.col.f32.tf32.tf32.f32 "
        "{%0,%1,%2,%3},{%4,%5,%6,%7},{%8,%9},{%0,%1,%2,%3};\n"
        : "+f"(c[0]), "+f"(c[1]), "+f"(c[2]), "+f"(c[3])
        : "r"(a0), "r"(a1), "r"(a2), "r"(a3), "r"(b0), "r"(b1));
}

// ---------------------------------------------------------------------------
// Kernel A: bunch attention (warp per x-token) + LN1 -> g_z1  (unchanged R4)
// ---------------------------------------------------------------------------
template <int TO>
__device__ __forceinline__ void attn_body(
    const float* __restrict__ u, const float* __restrict__ x,
    const float* sWq, const float* sWkT, const float* sWvT,
    const float* sbq, const float* sbk, const float* sbv,
    const float* sg1, const float* sbe1,
    float* myLog, float* myUb, int b, int n, int l)
{
    int t, S0, S1;
    if (TO == 4)      { t = n;        S0 = 0;     S1 = 24576; }
    else if (TO == 8) { t = n - 4096; S0 = 8192;  S1 = 32768; }
    else              { t = n - 6144; S0 = 16384; S1 = 40960; }
    int cidx = t * TO;
    int base = (cidx < 8192) ? (S0 + cidx) : (S1 + cidx - 8192);
    const float* uptr = u + ((size_t)b * Uu + base) * Cc;
    const float* xptr = x + ((size_t)b * Nn + n) * Cc;

    float xv0 = xptr[l], xv1 = xptr[l + 32];

    float q0a = sbq[l], q1a = sbq[l + 32], q0b = 0.f, q1b = 0.f;
#pragma unroll
    for (int in = 0; in < 32; in++) {
        float xb = __shfl_sync(FULLMASK, xv0, in);
        if (in & 1) { q0b += xb * sWq[in * 64 + l]; q1b += xb * sWq[in * 64 + l + 32]; }
        else        { q0a += xb * sWq[in * 64 + l]; q1a += xb * sWq[in * 64 + l + 32]; }
    }
#pragma unroll
    for (int in = 0; in < 32; in++) {
        float xb = __shfl_sync(FULLMASK, xv1, in);
        if (in & 1) { q0b += xb * sWq[(in + 32) * 64 + l]; q1b += xb * sWq[(in + 32) * 64 + l + 32]; }
        else        { q0a += xb * sWq[(in + 32) * 64 + l]; q1a += xb * sWq[(in + 32) * 64 + l + 32]; }
    }
    float q0 = (q0a + q0b) * 0.125f;
    float q1 = (q1a + q1b) * 0.125f;

    float w0[4] = {0.f, 0.f, 0.f, 0.f}, w1[4] = {0.f, 0.f, 0.f, 0.f};
    float bkq[4] = {0.f, 0.f, 0.f, 0.f};
#pragma unroll
    for (int oc = 0; oc < 32; oc++) {
        float qb = __shfl_sync(FULLMASK, q0, oc);
        const int g = oc >> 4;
        w0[g] += qb * sWkT[oc * 65 + l];
        w1[g] += qb * sWkT[oc * 65 + l + 32];
        bkq[g] += qb * sbk[oc];
    }
#pragma unroll
    for (int oc = 32; oc < 64; oc++) {
        float qb = __shfl_sync(FULLMASK, q1, oc - 32);
        const int g = oc >> 4;
        w0[g] += qb * sWkT[oc * 65 + l];
        w1[g] += qb * sWkT[oc * 65 + l + 32];
        bkq[g] += qb * sbk[oc];
    }

    float ur0[TO], ur1[TO];
#pragma unroll
    for (int r = 0; r < TO; r++) {
        ur0[r] = uptr[r * 64 + l];
        ur1[r] = uptr[r * 64 + l + 32];
    }

#pragma unroll
    for (int r = 0; r < TO; r++) {
        float p0 = ur0[r] * w0[0] + ur1[r] * w1[0];
        float p1 = ur0[r] * w0[1] + ur1[r] * w1[1];
        float p2 = ur0[r] * w0[2] + ur1[r] * w1[2];
        float p3 = ur0[r] * w0[3] + ur1[r] * w1[3];
#pragma unroll
        for (int off = 16; off; off >>= 1) {
            p0 += __shfl_xor_sync(FULLMASK, p0, off);
            p1 += __shfl_xor_sync(FULLMASK, p1, off);
            p2 += __shfl_xor_sync(FULLMASK, p2, off);
            p3 += __shfl_xor_sync(FULLMASK, p3, off);
        }
        if (l == 0) {
            myLog[r * 4 + 0] = p0 + bkq[0];
            myLog[r * 4 + 1] = p1 + bkq[1];
            myLog[r * 4 + 2] = p2 + bkq[2];
            myLog[r * 4 + 3] = p3 + bkq[3];
        }
    }
    __syncwarp();

    if (l < 4) {
        float m = -1e30f;
#pragma unroll
        for (int r = 0; r < TO; r++) m = fmaxf(m, myLog[r * 4 + l]);
        float s = 0.f;
#pragma unroll
        for (int r = 0; r < TO; r++) {
            float e = __expf(myLog[r * 4 + l] - m);
            s += e;
            myLog[r * 4 + l] = e;
        }
        float inv = 1.f / s;
#pragma unroll
        for (int r = 0; r < TO; r++) myLog[r * 4 + l] *= inv;
    }
    __syncwarp();

    float ub0[4] = {0.f, 0.f, 0.f, 0.f}, ub1[4] = {0.f, 0.f, 0.f, 0.f};
#pragma unroll
    for (int r = 0; r < TO; r++) {
        float pg0 = myLog[r * 4 + 0], pg1 = myLog[r * 4 + 1];
        float pg2 = myLog[r * 4 + 2], pg3 = myLog[r * 4 + 3];
        ub0[0] += pg0 * ur0[r]; ub1[0] += pg0 * ur1[r];
        ub0[1] += pg1 * ur0[r]; ub1[1] += pg1 * ur1[r];
        ub0[2] += pg2 * ur0[r]; ub1[2] += pg2 * ur1[r];
        ub0[3] += pg3 * ur0[r]; ub1[3] += pg3 * ur1[r];
    }

    __syncwarp();
#pragma unroll
    for (int g = 0; g < 4; g++) {
        myUb[g * 68 + l]      = ub0[g];
        myUb[g * 68 + 32 + l] = ub1[g];
    }
    __syncwarp();

    const int ga = l >> 4;
    const int gb = ga + 2;
    float av0 = sbv[l], av1 = sbv[l + 32];
#pragma unroll
    for (int in = 0; in < 64; in += 4) {
        float4 ua = *(const float4*)&myUb[ga * 68 + in];
        float4 ub = *(const float4*)&myUb[gb * 68 + in];
        float4 wa = *(const float4*)&sWvT[l * 68 + in];
        float4 wb = *(const float4*)&sWvT[(l + 32) * 68 + in];
        av0 = dot4(ua, wa, av0);
        av1 = dot4(ub, wb, av1);
    }

    float mean = warp_sum(av0 + av1) * (1.f / 64.f);
    float d0 = av0 - mean, d1 = av1 - mean;
    float var = warp_sum(d0 * d0 + d1 * d1) * (1.f / 64.f);
    float inv = rsqrtf(var + 1e-5f);
    size_t o = ((size_t)b * Nn + n) * Cc;
    g_z1[o + l]      = d0 * inv * sg1[l]      + sbe1[l];
    g_z1[o + l + 32] = d1 * inv * sg1[l + 32] + sbe1[l + 32];
}

extern "C" __global__ void __launch_bounds__(256)
kernelA(const float* __restrict__ u, const float* __restrict__ x,
        const float* __restrict__ Wk, const float* __restrict__ bk,
        const float* __restrict__ Wq, const float* __restrict__ bq,
        const float* __restrict__ Wv, const float* __restrict__ bv,
        const float* __restrict__ g1, const float* __restrict__ be1)
{
    extern __shared__ float sm[];
    float* sWq  = sm;
    float* sWkT = sm + 4096;
    float* sWvT = sm + 4096 + 4160;
    float* sbq  = sWvT + 4352;
    float* sbk  = sbq + 64;
    float* sbv  = sbk + 64;
    float* sg1  = sbv + 64;
    float* sbe1 = sg1 + 64;
    float* sLog = sbe1 + 64;
    float* sUb  = sLog + 512;

    int tid = threadIdx.x;
    for (int i = tid; i < 4096; i += 256) {
        sWq[i] = Wq[i];
        int in = i >> 6, oc = i & 63;
        sWkT[oc * 65 + in] = Wk[i];
        sWvT[oc * 68 + in] = Wv[i];
    }
    if (tid < 64) {
        sbq[tid] = bq[tid]; sbk[tid] = bk[tid]; sbv[tid] = bv[tid];
        sg1[tid] = g1[tid]; sbe1[tid] = be1[tid];
    }
    __syncthreads();

    int warp = tid >> 5, l = tid & 31;
    float* myLog = sLog + warp * 64;
    float* myUb  = sUb + warp * 272;

    for (int blk = blockIdx.x; blk < (Bb * Nn / 8); blk += gridDim.x) {
        int token = blk * 8 + warp;
        int b = token / Nn, n = token % Nn;
        int n0 = (blk % (Nn / 8)) * 8;
        if (n0 < 4096)
            attn_body<4>(u, x, sWq, sWkT, sWvT, sbq, sbk, sbv, sg1, sbe1, myLog, myUb, b, n, l);
        else if (n0 < 6144)
            attn_body<8>(u, x, sWq, sWkT, sWvT, sbq, sbk, sbv, sg1, sbe1, myLog, myUb, b, n, l);
        else
            attn_body<16>(u, x, sWq, sWkT, sWvT, sbq, sbk, sbv, sg1, sbe1, myLog, myUb, b, n, l);
    }
}

// ---------------------------------------------------------------------------
// Kernel B (tf32 tensor cores): MLP + LN2 + shortcut
//   GEMM1: H = gelu(Z[32x64] @ Wm1[64x256] + bm1)
//   GEMM2: O = H[32x256] @ Wm2[256x64] + bm2
//   GEMM3: S = X[32x64]  @ Ws [64x64]  + bs
//   out = LN2(O) + S
// 512 threads = 16 warps = 2 m-tiles x 8 n-groups. mma.m16n8k8 tf32.
// ---------------------------------------------------------------------------
constexpr int P_WM1 = 264;  // pitch of Wm1 in smem (bank-conflict-free B frags)
constexpr int P_WM2 = 72;
constexpr int P_WS  = 72;
constexpr int P_Z   = 68;   // conflict-free A frags
constexpr int P_H   = 260;

extern "C" __global__ void __launch_bounds__(512)
kernelB(const float* __restrict__ x,
        const float* __restrict__ Wm1, const float* __restrict__ bm1,
        const float* __restrict__ Wm2, const float* __restrict__ bm2,
        const float* __restrict__ g2,  const float* __restrict__ be2,
        const float* __restrict__ Ws,  const float* __restrict__ bs,
        float* __restrict__ out)
{
    extern __shared__ float sm[];
    float* sWm1f = sm;                    // 64 * 264 = 16896
    float* sWm2f = sWm1f + 64 * P_WM1;    // 256 * 72 = 18432
    float* sWsf  = sWm2f + 256 * P_WM2;   // 64 * 72  = 4608
    float* sbm1  = sWsf + 64 * P_WS;      // 256
    float* sbm2  = sbm1 + 256;            // 64
    float* sg2   = sbm2 + 64;
    float* sbe2  = sg2 + 64;
    float* sbs   = sbe2 + 64;
    float* sZ    = sbs + 64;              // 32 * 68 = 2176
    float* sX    = sZ + 32 * P_Z;         // 32 * 68 = 2176
    float* sH    = sX + 32 * P_Z;         // 32 * 260 = 8320
    float* sRedS = sH + 32 * P_H;         // 32 * 8 = 256
    float* sRedQ = sRedS + 256;           // 256

    int tid = threadIdx.x;
    // weights -> smem, rounded to tf32 once per CTA
    for (int i = tid; i < 64 * 256; i += 512) {
        int k = i >> 8, n = i & 255;
        sWm1f[k * P_WM1 + n] = to_tf32(Wm1[i]);
    }
    for (int i = tid; i < 256 * 64; i += 512) {
        int k = i >> 6, n = i & 63;
        sWm2f[k * P_WM2 + n] = to_tf32(Wm2[i]);
    }
    for (int i = tid; i < 64 * 64; i += 512) {
        int k = i >> 6, n = i & 63;
        sWsf[k * P_WS + n] = to_tf32(Ws[i]);
    }
    if (tid < 256) sbm1[tid] = bm1[tid];
    if (tid < 64) { sbm2[tid] = bm2[tid]; sg2[tid] = g2[tid]; sbe2[tid] = be2[tid]; sbs[tid] = bs[tid]; }
    __syncthreads();

    const int warp = tid >> 5, lane = tid & 31;
    const int wm = warp >> 3, wn = warp & 7;      // 2 m-tiles x 8 n-groups
    const int lq = lane >> 2, lr = lane & 3;      // lane quad-row / quad-col
    const int row_lo = wm * 16 + lq;              // D-frag rows
    const int row_hi = row_lo + 8;
    const int NTILES = Bb * Nn / 32;              // 1792

    for (int tile = blockIdx.x; tile < NTILES; tile += gridDim.x) {
        size_t base = (size_t)tile * 32 * 64;
        // load Z, X tiles -> smem (tf32-rounded), one float4 per thread
        {
            int row = tid >> 4, seg = (tid & 15) * 4;
            float4 z4 = *(const float4*)(g_z1 + base + row * 64 + seg);
            float4 x4 = *(const float4*)(x + base + row * 64 + seg);
            z4.x = to_tf32(z4.x); z4.y = to_tf32(z4.y); z4.z = to_tf32(z4.z); z4.w = to_tf32(z4.w);
            x4.x = to_tf32(x4.x); x4.y = to_tf32(x4.y); x4.z = to_tf32(x4.z); x4.w = to_tf32(x4.w);
            *(float4*)&sZ[row * P_Z + seg] = z4;
            *(float4*)&sX[row * P_Z + seg] = x4;
        }
        __syncthreads();

        // ---- GEMM1: 4 n-tiles per warp over K=64 ----
        float c[4][4];
#pragma unroll
        for (int nt = 0; nt < 4; nt++)
#pragma unroll
            for (int j = 0; j < 4; j++) c[nt][j] = 0.f;

        const float* A1 = sZ + (wm * 16 + lq) * P_Z + lr;
#pragma unroll
        for (int k0 = 0; k0 < 64; k0 += 8) {
            uint32_t a0 = __float_as_uint(A1[k0]);
            uint32_t a1 = __float_as_uint(A1[k0 + 8 * P_Z]);
            uint32_t a2 = __float_as_uint(A1[k0 + 4]);
            uint32_t a3 = __float_as_uint(A1[k0 + 8 * P_Z + 4]);
            const float* B1 = sWm1f + (k0 + lr) * P_WM1 + wn * 32 + lq;
#pragma unroll
            for (int nt = 0; nt < 4; nt++) {
                uint32_t b0 = __float_as_uint(B1[nt * 8]);
                uint32_t b1 = __float_as_uint(B1[4 * P_WM1 + nt * 8]);
                mma_tf32(c[nt], a0, a1, a2, a3, b0, b1);
            }
        }
        // bias + gelu + store H (tf32-rounded)
#pragma unroll
        for (int nt = 0; nt < 4; nt++) {
            int col = wn * 32 + nt * 8 + lr * 2;
            float v0 = c[nt][0] + sbm1[col];
            float v1 = c[nt][1] + sbm1[col + 1];
            float v2 = c[nt][2] + sbm1[col];
            float v3 = c[nt][3] + sbm1[col + 1];
            sH[row_lo * P_H + col]     = to_tf32(v0 * 0.5f * (1.f + erff(v0 * 0.70710678118654752f)));
            sH[row_lo * P_H + col + 1] = to_tf32(v1 * 0.5f * (1.f + erff(v1 * 0.70710678118654752f)));
            sH[row_hi * P_H + col]     = to_tf32(v2 * 0.5f * (1.f + erff(v2 * 0.70710678118654752f)));
            sH[row_hi * P_H + col + 1] = to_tf32(v3 * 0.5f * (1.f + erff(v3 * 0.70710678118654752f)));
        }
        __syncthreads();

        // ---- GEMM2 (K=256) and GEMM3 (K=64), one 8-col n-tile per warp ----
        float o[4] = {0.f, 0.f, 0.f, 0.f};
        float s[4] = {0.f, 0.f, 0.f, 0.f};
        const float* A2 = sH + (wm * 16 + lq) * P_H + lr;
        const float* B2 = sWm2f + lr * P_WM2 + wn * 8 + lq;
#pragma unroll
        for (int k0 = 0; k0 < 256; k0 += 8) {
            uint32_t a0 = __float_as_uint(A2[k0]);
            uint32_t a1 = __float_as_uint(A2[k0 + 8 * P_H]);
            uint32_t a2 = __float_as_uint(A2[k0 + 4]);
            uint32_t a3 = __float_as_uint(A2[k0 + 8 * P_H + 4]);
            uint32_t b0 = __float_as_uint(B2[k0 * P_WM2]);
            uint32_t b1 = __float_as_uint(B2[(k0 + 4) * P_WM2]);
            mma_tf32(o, a0, a1, a2, a3, b0, b1);
        }
        const float* A3 = sX + (wm * 16 + lq) * P_Z + lr;
        const float* B3 = sWsf + lr * P_WS + wn * 8 + lq;
#pragma unroll
        for (int k0 = 0; k0 < 64; k0 += 8) {
            uint32_t a0 = __float_as_uint(A3[k0]);
            uint32_t a1 = __float_as_uint(A3[k0 + 8 * P_Z]);
            uint32_t a2 = __float_as_uint(A3[k0 + 4]);
            uint32_t a3 = __float_as_uint(A3[k0 + 8 * P_Z + 4]);
            uint32_t b0 = __float_as_uint(B3[k0 * P_WS]);
            uint32_t b1 = __float_as_uint(B3[(k0 + 4) * P_WS]);
            mma_tf32(s, a0, a1, a2, a3, b0, b1);
        }

        // bias for O, then per-row partial sums for LN2
        int col = wn * 8 + lr * 2;
        o[0] += sbm2[col]; o[1] += sbm2[col + 1];
        o[2] += sbm2[col]; o[3] += sbm2[col + 1];

        float slo = o[0] + o[1], shi = o[2] + o[3];
        float qlo = o[0] * o[0] + o[1] * o[1], qhi = o[2] * o[2] + o[3] * o[3];
#pragma unroll
        for (int off = 1; off <= 2; off <<= 1) {
            slo += __shfl_xor_sync(FULLMASK, slo, off);
            shi += __shfl_xor_sync(FULLMASK, shi, off);
            qlo += __shfl_xor_sync(FULLMASK, qlo, off);
            qhi += __shfl_xor_sync(FULLMASK, qhi, off);
        }
        if (lr == 0) {
            sRedS[row_lo * 8 + wn] = slo;  sRedQ[row_lo * 8 + wn] = qlo;
            sRedS[row_hi * 8 + wn] = shi;  sRedQ[row_hi * 8 + wn] = qhi;
        }
        __syncthreads();

        // LN2 + gamma/beta + shortcut + store
        float ms_lo = 0.f, mq_lo = 0.f, ms_hi = 0.f, mq_hi = 0.f;
#pragma unroll
        for (int j = 0; j < 8; j++) {
            ms_lo += sRedS[row_lo * 8 + j];  mq_lo += sRedQ[row_lo * 8 + j];
            ms_hi += sRedS[row_hi * 8 + j];  mq_hi += sRedQ[row_hi * 8 + j];
        }
        float mean_lo = ms_lo * (1.f / 64.f);
        float mean_hi = ms_hi * (1.f / 64.f);
        float inv_lo = rsqrtf(mq_lo * (1.f / 64.f) - mean_lo * mean_lo + 1e-5f);
        float inv_hi = rsqrtf(mq_hi * (1.f / 64.f) - mean_hi * mean_hi + 1e-5f);

        float g0 = sg2[col], g1v = sg2[col + 1];
        float e0 = sbe2[col], e1 = sbe2[col + 1];
        float bs0 = sbs[col], bs1 = sbs[col + 1];

        float2 r_lo, r_hi;
        r_lo.x = (o[0] - mean_lo) * inv_lo * g0  + e0 + s[0] + bs0;
        r_lo.y = (o[1] - mean_lo) * inv_lo * g1v + e1 + s[1] + bs1;
        r_hi.x = (o[2] - mean_hi) * inv_hi * g0  + e0 + s[2] + bs0;
        r_hi.y = (o[3] - mean_hi) * inv_hi * g1v + e1 + s[3] + bs1;

        *(float2*)(out + base + (size_t)row_lo * 64 + col) = r_lo;
        *(float2*)(out + base + (size_t)row_hi * 64 + col) = r_hi;
        __syncthreads();
    }
}

// ---------------------------------------------------------------------------
extern "C" void kernel_launch(void* const* d_in, const int* in_sizes, int n_in,
                              void* d_out, int out_size)
{
    const float* u   = (const float*)d_in[0];
    const float* x   = (const float*)d_in[1];
    const float* Wk  = (const float*)d_in[2];
    const float* bk  = (const float*)d_in[3];
    const float* Wq  = (const float*)d_in[4];
    const float* bq  = (const float*)d_in[5];
    const float* Wv  = (const float*)d_in[6];
    const float* bv  = (const float*)d_in[7];
    const float* g1  = (const float*)d_in[8];
    const float* be1 = (const float*)d_in[9];
    const float* Wm1 = (const float*)d_in[10];
    const float* bm1 = (const float*)d_in[11];
    const float* Wm2 = (const float*)d_in[12];
    const float* bm2 = (const float*)d_in[13];
    const float* g2  = (const float*)d_in[14];
    const float* be2 = (const float*)d_in[15];
    const float* Ws  = (const float*)d_in[16];
    const float* bs  = (const float*)d_in[17];
    float* out = (float*)d_out;

    const int smemA = (4096 + 4160 + 4352 + 5 * 64 + 512 + 2176) * 4;  // 62464 B
    const int smemB = (64 * P_WM1 + 256 * P_WM2 + 64 * P_WS + 256 + 4 * 64 +
                       2 * 32 * P_Z + 32 * P_H + 512) * 4;              // ~206 KB

    cudaFuncSetAttribute(kernelA, cudaFuncAttributeMaxDynamicSharedMemorySize, smemA);
    cudaFuncSetAttribute(kernelB, cudaFuncAttributeMaxDynamicSharedMemorySize, smemB);

    kernelA<<<444, 256, smemA>>>(u, x, Wk, bk, Wq, bq, Wv, bv, g1, be1);
    kernelB<<<148, 512, smemB>>>(x, Wm1, bm1, Wm2, bm2, g2, be2, Ws, bs, out);
}

// round 7
// speedup vs baseline: 1.7287x; 1.1181x over previous
#include <cuda_runtime.h>
#include <math.h>
#include <stdint.h>

#define FULLMASK 0xffffffffu

constexpr int Bb = 8;
constexpr int Nn = 7168;
constexpr int Uu = 49152;
constexpr int Cc = 64;

// scratch: post-LN1 attention output
__device__ float g_z1[Bb * Nn * Cc];

__device__ __forceinline__ float warp_sum(float v) {
#pragma unroll
    for (int off = 16; off; off >>= 1) v += __shfl_xor_sync(FULLMASK, v, off);
    return v;
}

__device__ __forceinline__ float dot4(float4 a, float4 b, float acc) {
    acc = fmaf(a.x, b.x, acc);
    acc = fmaf(a.y, b.y, acc);
    acc = fmaf(a.z, b.z, acc);
    acc = fmaf(a.w, b.w, acc);
    return acc;
}

__device__ __forceinline__ float to_tf32(float x) {
    uint32_t r;
    asm("cvt.rna.tf32.f32 %0, %1;" : "=r"(r) : "f"(x));
    return __uint_as_float(r);
}

__device__ __forceinline__ void mma_tf32(float c[4],
    uint32_t a0, uint32_t a1, uint32_t a2, uint32_t a3,
    uint32_t b0, uint32_t b1)
{
    asm volatile(
        "mma.sync.aligned.m16n8k8.row.col.f32.tf32.tf32.f32 "
        "{%0,%1,%2,%3},{%4,%5,%6,%7},{%8,%9},{%0,%1,%2,%3};\n"
        : "+f"(c[0]), "+f"(c[1]), "+f"(c[2]), "+f"(c[3])
        : "r"(a0), "r"(a1), "r"(a2), "r"(a3), "r"(b0), "r"(b1));
}

// ---------------------------------------------------------------------------
// Kernel A: bunch attention (warp per x-token) + LN1 -> g_z1
// ---------------------------------------------------------------------------
template <int TO>
__device__ __forceinline__ void attn_body(
    const float* __restrict__ u, const float* __restrict__ x,
    const float* __restrict__ Wq,
    const float* sWkT, const float* sWvT,
    const float* sbq, const float* sbk, const float* sbv,
    const float* sg1, const float* sbe1,
    float* myLog, float* myUb, int b, int n, int l)
{
    int t, S0, S1;
    if (TO == 4)      { t = n;        S0 = 0;     S1 = 24576; }
    else if (TO == 8) { t = n - 4096; S0 = 8192;  S1 = 32768; }
    else              { t = n - 6144; S0 = 16384; S1 = 40960; }
    int cidx = t * TO;
    int base = (cidx < 8192) ? (S0 + cidx) : (S1 + cidx - 8192);
    const float* uptr = u + ((size_t)b * Uu + base) * Cc;
    const float* xptr = x + ((size_t)b * Nn + n) * Cc;

    float xv0 = xptr[l], xv1 = xptr[l + 32];

    // q[out] = bq + x @ Wq (scale 1/8 folded); Wq read via L1 (global)
    float q0a = sbq[l], q1a = sbq[l + 32], q0b = 0.f, q1b = 0.f;
#pragma unroll
    for (int in = 0; in < 32; in++) {
        float xb = __shfl_sync(FULLMASK, xv0, in);
        if (in & 1) { q0b += xb * Wq[in * 64 + l]; q1b += xb * Wq[in * 64 + l + 32]; }
        else        { q0a += xb * Wq[in * 64 + l]; q1a += xb * Wq[in * 64 + l + 32]; }
    }
#pragma unroll
    for (int in = 0; in < 32; in++) {
        float xb = __shfl_sync(FULLMASK, xv1, in);
        if (in & 1) { q0b += xb * Wq[(in + 32) * 64 + l]; q1b += xb * Wq[(in + 32) * 64 + l + 32]; }
        else        { q0a += xb * Wq[(in + 32) * 64 + l]; q1a += xb * Wq[(in + 32) * 64 + l + 32]; }
    }
    float q0 = (q0a + q0b) * 0.125f;
    float q1 = (q1a + q1b) * 0.125f;

    // w[g][in] = sum_{oc in group g} Wk[in][oc] * q[oc]   (and bk·q per group)
    float w0[4] = {0.f, 0.f, 0.f, 0.f}, w1[4] = {0.f, 0.f, 0.f, 0.f};
    float bkq[4] = {0.f, 0.f, 0.f, 0.f};
#pragma unroll
    for (int oc = 0; oc < 32; oc++) {
        float qb = __shfl_sync(FULLMASK, q0, oc);
        const int g = oc >> 4;
        w0[g] += qb * sWkT[oc * 65 + l];
        w1[g] += qb * sWkT[oc * 65 + l + 32];
        bkq[g] += qb * sbk[oc];
    }
#pragma unroll
    for (int oc = 32; oc < 64; oc++) {
        float qb = __shfl_sync(FULLMASK, q1, oc - 32);
        const int g = oc >> 4;
        w0[g] += qb * sWkT[oc * 65 + l];
        w1[g] += qb * sWkT[oc * 65 + l + 32];
        bkq[g] += qb * sbk[oc];
    }

    // load the TO contiguous u rows into registers
    float ur0[TO], ur1[TO];
#pragma unroll
    for (int r = 0; r < TO; r++) {
        ur0[r] = uptr[r * 64 + l];
        ur1[r] = uptr[r * 64 + l + 32];
    }

    // bkq select for lanes 0..3 (avoids dynamic local-array indexing)
    float bk_sel = bkq[0];
    if (l == 1) bk_sel = bkq[1];
    if (l == 2) bk_sel = bkq[2];
    if (l == 3) bk_sel = bkq[3];

    // logits: 6-shfl multi-value reduction (p0..p3 reduced simultaneously)
#pragma unroll
    for (int r = 0; r < TO; r++) {
        float p0 = ur0[r] * w0[0] + ur1[r] * w1[0];
        float p1 = ur0[r] * w0[1] + ur1[r] * w1[1];
        float p2 = ur0[r] * w0[2] + ur1[r] * w1[2];
        float p3 = ur0[r] * w0[3] + ur1[r] * w1[3];
        // fold p0/p1 across xor-1
        float t0 = (l & 1) ? p0 : p1;
        float r0 = __shfl_xor_sync(FULLMASK, t0, 1);
        float a = ((l & 1) ? p1 : p0) + r0;
        // fold p2/p3 across xor-1
        float t1 = (l & 1) ? p2 : p3;
        float r1 = __shfl_xor_sync(FULLMASK, t1, 1);
        float bq_ = ((l & 1) ? p3 : p2) + r1;
        // fold a/b across xor-2
        float t2 = (l & 2) ? a : bq_;
        float r2 = __shfl_xor_sync(FULLMASK, t2, 2);
        float c = ((l & 2) ? bq_ : a) + r2;
        // shared butterfly: lane ends with full sum of p_{l&3}
        c += __shfl_xor_sync(FULLMASK, c, 4);
        c += __shfl_xor_sync(FULLMASK, c, 8);
        c += __shfl_xor_sync(FULLMASK, c, 16);
        if (l < 4) myLog[r * 4 + l] = c + bk_sel;
    }
    __syncwarp();

    // softmax over r, one group per lane (lanes 0..3)
    if (l < 4) {
        float m = -1e30f;
#pragma unroll
        for (int r = 0; r < TO; r++) m = fmaxf(m, myLog[r * 4 + l]);
        float s = 0.f;
#pragma unroll
        for (int r = 0; r < TO; r++) {
            float e = __expf(myLog[r * 4 + l] - m);
            s += e;
            myLog[r * 4 + l] = e;
        }
        float inv = 1.f / s;
#pragma unroll
        for (int r = 0; r < TO; r++) myLog[r * 4 + l] *= inv;
    }
    __syncwarp();

    // ubar[g] = sum_r p[r][g] * u_r   (per-channel in each lane)
    float ub0[4] = {0.f, 0.f, 0.f, 0.f}, ub1[4] = {0.f, 0.f, 0.f, 0.f};
#pragma unroll
    for (int r = 0; r < TO; r++) {
        float pg0 = myLog[r * 4 + 0], pg1 = myLog[r * 4 + 1];
        float pg2 = myLog[r * 4 + 2], pg3 = myLog[r * 4 + 3];
        ub0[0] += pg0 * ur0[r]; ub1[0] += pg0 * ur1[r];
        ub0[1] += pg1 * ur0[r]; ub1[1] += pg1 * ur1[r];
        ub0[2] += pg2 * ur0[r]; ub1[2] += pg2 * ur1[r];
        ub0[3] += pg3 * ur0[r]; ub1[3] += pg3 * ur1[r];
    }

    // stage ubar to per-warp smem, v-proj via float4 reads
    __syncwarp();
#pragma unroll
    for (int g = 0; g < 4; g++) {
        myUb[g * 68 + l]      = ub0[g];
        myUb[g * 68 + 32 + l] = ub1[g];
    }
    __syncwarp();

    const int ga = l >> 4;
    const int gb = ga + 2;
    float av0 = sbv[l], av1 = sbv[l + 32];
#pragma unroll
    for (int in = 0; in < 64; in += 4) {
        float4 ua = *(const float4*)&myUb[ga * 68 + in];
        float4 ub = *(const float4*)&myUb[gb * 68 + in];
        float4 wa = *(const float4*)&sWvT[l * 68 + in];
        float4 wb = *(const float4*)&sWvT[(l + 32) * 68 + in];
        av0 = dot4(ua, wa, av0);
        av1 = dot4(ub, wb, av1);
    }

    // LN1 and write to scratch
    float mean = warp_sum(av0 + av1) * (1.f / 64.f);
    float d0 = av0 - mean, d1 = av1 - mean;
    float var = warp_sum(d0 * d0 + d1 * d1) * (1.f / 64.f);
    float inv = rsqrtf(var + 1e-5f);
    size_t o = ((size_t)b * Nn + n) * Cc;
    g_z1[o + l]      = d0 * inv * sg1[l]      + sbe1[l];
    g_z1[o + l + 32] = d1 * inv * sg1[l + 32] + sbe1[l + 32];
}

extern "C" __global__ void __launch_bounds__(256, 4)
kernelA(const float* __restrict__ u, const float* __restrict__ x,
        const float* __restrict__ Wk, const float* __restrict__ bk,
        const float* __restrict__ Wq, const float* __restrict__ bq,
        const float* __restrict__ Wv, const float* __restrict__ bv,
        const float* __restrict__ g1, const float* __restrict__ be1)
{
    extern __shared__ float sm[];
    float* sWkT = sm;                 // 64*65 = 4160 (pitch 65)
    float* sWvT = sm + 4160;          // 64*68 = 4352 (pitch 68)
    float* sbq  = sWvT + 4352;
    float* sbk  = sbq + 64;
    float* sbv  = sbk + 64;
    float* sg1  = sbv + 64;
    float* sbe1 = sg1 + 64;
    float* sLog = sbe1 + 64;          // 8 warps * 64
    float* sUb  = sLog + 512;         // 8 warps * 272

    int tid = threadIdx.x;
    for (int i = tid; i < 4096; i += 256) {
        int in = i >> 6, oc = i & 63;
        sWkT[oc * 65 + in] = Wk[i];
        sWvT[oc * 68 + in] = Wv[i];
    }
    if (tid < 64) {
        sbq[tid] = bq[tid]; sbk[tid] = bk[tid]; sbv[tid] = bv[tid];
        sg1[tid] = g1[tid]; sbe1[tid] = be1[tid];
    }
    __syncthreads();

    int warp = tid >> 5, l = tid & 31;
    float* myLog = sLog + warp * 64;
    float* myUb  = sUb + warp * 272;

    for (int blk = blockIdx.x; blk < (Bb * Nn / 8); blk += gridDim.x) {
        int token = blk * 8 + warp;
        int b = token / Nn, n = token % Nn;
        int n0 = (blk % (Nn / 8)) * 8;
        if (n0 < 4096)
            attn_body<4>(u, x, Wq, sWkT, sWvT, sbq, sbk, sbv, sg1, sbe1, myLog, myUb, b, n, l);
        else if (n0 < 6144)
            attn_body<8>(u, x, Wq, sWkT, sWvT, sbq, sbk, sbv, sg1, sbe1, myLog, myUb, b, n, l);
        else
            attn_body<16>(u, x, Wq, sWkT, sWvT, sbq, sbk, sbv, sg1, sbe1, myLog, myUb, b, n, l);
    }
}

// ---------------------------------------------------------------------------
// Kernel B (tf32 tensor cores): MLP + LN2 + shortcut  (unchanged from R5)
// ---------------------------------------------------------------------------
constexpr int P_WM1 = 264;
constexpr int P_WM2 = 72;
constexpr int P_WS  = 72;
constexpr int P_Z   = 68;
constexpr int P_H   = 260;

extern "C" __global__ void __launch_bounds__(512)
kernelB(const float* __restrict__ x,
        const float* __restrict__ Wm1, const float* __restrict__ bm1,
        const float* __restrict__ Wm2, const float* __restrict__ bm2,
        const float* __restrict__ g2,  const float* __restrict__ be2,
        const float* __restrict__ Ws,  const float* __restrict__ bs,
        float* __restrict__ out)
{
    extern __shared__ float sm[];
    float* sWm1f = sm;
    float* sWm2f = sWm1f + 64 * P_WM1;
    float* sWsf  = sWm2f + 256 * P_WM2;
    float* sbm1  = sWsf + 64 * P_WS;
    float* sbm2  = sbm1 + 256;
    float* sg2   = sbm2 + 64;
    float* sbe2  = sg2 + 64;
    float* sbs   = sbe2 + 64;
    float* sZ    = sbs + 64;
    float* sX    = sZ + 32 * P_Z;
    float* sH    = sX + 32 * P_Z;
    float* sRedS = sH + 32 * P_H;
    float* sRedQ = sRedS + 256;

    int tid = threadIdx.x;
    for (int i = tid; i < 64 * 256; i += 512) {
        int k = i >> 8, n = i & 255;
        sWm1f[k * P_WM1 + n] = to_tf32(Wm1[i]);
    }
    for (int i = tid; i < 256 * 64; i += 512) {
        int k = i >> 6, n = i & 63;
        sWm2f[k * P_WM2 + n] = to_tf32(Wm2[i]);
    }
    for (int i = tid; i < 64 * 64; i += 512) {
        int k = i >> 6, n = i & 63;
        sWsf[k * P_WS + n] = to_tf32(Ws[i]);
    }
    if (tid < 256) sbm1[tid] = bm1[tid];
    if (tid < 64) { sbm2[tid] = bm2[tid]; sg2[tid] = g2[tid]; sbe2[tid] = be2[tid]; sbs[tid] = bs[tid]; }
    __syncthreads();

    const int warp = tid >> 5, lane = tid & 31;
    const int wm = warp >> 3, wn = warp & 7;
    const int lq = lane >> 2, lr = lane & 3;
    const int row_lo = wm * 16 + lq;
    const int row_hi = row_lo + 8;
    const int NTILES = Bb * Nn / 32;

    for (int tile = blockIdx.x; tile < NTILES; tile += gridDim.x) {
        size_t base = (size_t)tile * 32 * 64;
        {
            int row = tid >> 4, seg = (tid & 15) * 4;
            float4 z4 = *(const float4*)(g_z1 + base + row * 64 + seg);
            float4 x4 = *(const float4*)(x + base + row * 64 + seg);
            z4.x = to_tf32(z4.x); z4.y = to_tf32(z4.y); z4.z = to_tf32(z4.z); z4.w = to_tf32(z4.w);
            x4.x = to_tf32(x4.x); x4.y = to_tf32(x4.y); x4.z = to_tf32(x4.z); x4.w = to_tf32(x4.w);
            *(float4*)&sZ[row * P_Z + seg] = z4;
            *(float4*)&sX[row * P_Z + seg] = x4;
        }
        __syncthreads();

        float c[4][4];
#pragma unroll
        for (int nt = 0; nt < 4; nt++)
#pragma unroll
            for (int j = 0; j < 4; j++) c[nt][j] = 0.f;

        const float* A1 = sZ + (wm * 16 + lq) * P_Z + lr;
#pragma unroll
        for (int k0 = 0; k0 < 64; k0 += 8) {
            uint32_t a0 = __float_as_uint(A1[k0]);
            uint32_t a1 = __float_as_uint(A1[k0 + 8 * P_Z]);
            uint32_t a2 = __float_as_uint(A1[k0 + 4]);
            uint32_t a3 = __float_as_uint(A1[k0 + 8 * P_Z + 4]);
            const float* B1 = sWm1f + (k0 + lr) * P_WM1 + wn * 32 + lq;
#pragma unroll
            for (int nt = 0; nt < 4; nt++) {
                uint32_t b0 = __float_as_uint(B1[nt * 8]);
                uint32_t b1 = __float_as_uint(B1[4 * P_WM1 + nt * 8]);
                mma_tf32(c[nt], a0, a1, a2, a3, b0, b1);
            }
        }
#pragma unroll
        for (int nt = 0; nt < 4; nt++) {
            int col = wn * 32 + nt * 8 + lr * 2;
            float v0 = c[nt][0] + sbm1[col];
            float v1 = c[nt][1] + sbm1[col + 1];
            float v2 = c[nt][2] + sbm1[col];
            float v3 = c[nt][3] + sbm1[col + 1];
            sH[row_lo * P_H + col]     = to_tf32(v0 * 0.5f * (1.f + erff(v0 * 0.70710678118654752f)));
            sH[row_lo * P_H + col + 1] = to_tf32(v1 * 0.5f * (1.f + erff(v1 * 0.70710678118654752f)));
            sH[row_hi * P_H + col]     = to_tf32(v2 * 0.5f * (1.f + erff(v2 * 0.70710678118654752f)));
            sH[row_hi * P_H + col + 1] = to_tf32(v3 * 0.5f * (1.f + erff(v3 * 0.70710678118654752f)));
        }
        __syncthreads();

        float o[4] = {0.f, 0.f, 0.f, 0.f};
        float s[4] = {0.f, 0.f, 0.f, 0.f};
        const float* A2 = sH + (wm * 16 + lq) * P_H + lr;
        const float* B2 = sWm2f + lr * P_WM2 + wn * 8 + lq;
#pragma unroll
        for (int k0 = 0; k0 < 256; k0 += 8) {
            uint32_t a0 = __float_as_uint(A2[k0]);
            uint32_t a1 = __float_as_uint(A2[k0 + 8 * P_H]);
            uint32_t a2 = __float_as_uint(A2[k0 + 4]);
            uint32_t a3 = __float_as_uint(A2[k0 + 8 * P_H + 4]);
            uint32_t b0 = __float_as_uint(B2[k0 * P_WM2]);
            uint32_t b1 = __float_as_uint(B2[(k0 + 4) * P_WM2]);
            mma_tf32(o, a0, a1, a2, a3, b0, b1);
        }
        const float* A3 = sX + (wm * 16 + lq) * P_Z + lr;
        const float* B3 = sWsf + lr * P_WS + wn * 8 + lq;
#pragma unroll
        for (int k0 = 0; k0 < 64; k0 += 8) {
            uint32_t a0 = __float_as_uint(A3[k0]);
            uint32_t a1 = __float_as_uint(A3[k0 + 8 * P_Z]);
            uint32_t a2 = __float_as_uint(A3[k0 + 4]);
            uint32_t a3 = __float_as_uint(A3[k0 + 8 * P_Z + 4]);
            uint32_t b0 = __float_as_uint(B3[k0 * P_WS]);
            uint32_t b1 = __float_as_uint(B3[(k0 + 4) * P_WS]);
            mma_tf32(s, a0, a1, a2, a3, b0, b1);
        }

        int col = wn * 8 + lr * 2;
        o[0] += sbm2[col]; o[1] += sbm2[col + 1];
        o[2] += sbm2[col]; o[3] += sbm2[col + 1];

        float slo = o[0] + o[1], shi = o[2] + o[3];
        float qlo = o[0] * o[0] + o[1] * o[1], qhi = o[2] * o[2] + o[3] * o[3];
#pragma unroll
        for (int off = 1; off <= 2; off <<= 1) {
            slo += __shfl_xor_sync(FULLMASK, slo, off);
            shi += __shfl_xor_sync(FULLMASK, shi, off);
            qlo += __shfl_xor_sync(FULLMASK, qlo, off);
            qhi += __shfl_xor_sync(FULLMASK, qhi, off);
        }
        if (lr == 0) {
            sRedS[row_lo * 8 + wn] = slo;  sRedQ[row_lo * 8 + wn] = qlo;
            sRedS[row_hi * 8 + wn] = shi;  sRedQ[row_hi * 8 + wn] = qhi;
        }
        __syncthreads();

        float ms_lo = 0.f, mq_lo = 0.f, ms_hi = 0.f, mq_hi = 0.f;
#pragma unroll
        for (int j = 0; j < 8; j++) {
            ms_lo += sRedS[row_lo * 8 + j];  mq_lo += sRedQ[row_lo * 8 + j];
            ms_hi += sRedS[row_hi * 8 + j];  mq_hi += sRedQ[row_hi * 8 + j];
        }
        float mean_lo = ms_lo * (1.f / 64.f);
        float mean_hi = ms_hi * (1.f / 64.f);
        float inv_lo = rsqrtf(mq_lo * (1.f / 64.f) - mean_lo * mean_lo + 1e-5f);
        float inv_hi = rsqrtf(mq_hi * (1.f / 64.f) - mean_hi * mean_hi + 1e-5f);

        float g0 = sg2[col], g1v = sg2[col + 1];
        float e0 = sbe2[col], e1 = sbe2[col + 1];
        float bs0 = sbs[col], bs1 = sbs[col + 1];

        float2 r_lo, r_hi;
        r_lo.x = (o[0] - mean_lo) * inv_lo * g0  + e0 + s[0] + bs0;
        r_lo.y = (o[1] - mean_lo) * inv_lo * g1v + e1 + s[1] + bs1;
        r_hi.x = (o[2] - mean_hi) * inv_hi * g0  + e0 + s[2] + bs0;
        r_hi.y = (o[3] - mean_hi) * inv_hi * g1v + e1 + s[3] + bs1;

        *(float2*)(out + base + (size_t)row_lo * 64 + col) = r_lo;
        *(float2*)(out + base + (size_t)row_hi * 64 + col) = r_hi;
        __syncthreads();
    }
}

// ---------------------------------------------------------------------------
extern "C" void kernel_launch(void* const* d_in, const int* in_sizes, int n_in,
                              void* d_out, int out_size)
{
    const float* u   = (const float*)d_in[0];
    const float* x   = (const float*)d_in[1];
    const float* Wk  = (const float*)d_in[2];
    const float* bk  = (const float*)d_in[3];
    const float* Wq  = (const float*)d_in[4];
    const float* bq  = (const float*)d_in[5];
    const float* Wv  = (const float*)d_in[6];
    const float* bv  = (const float*)d_in[7];
    const float* g1  = (const float*)d_in[8];
    const float* be1 = (const float*)d_in[9];
    const float* Wm1 = (const float*)d_in[10];
    const float* bm1 = (const float*)d_in[11];
    const float* Wm2 = (const float*)d_in[12];
    const float* bm2 = (const float*)d_in[13];
    const float* g2  = (const float*)d_in[14];
    const float* be2 = (const float*)d_in[15];
    const float* Ws  = (const float*)d_in[16];
    const float* bs  = (const float*)d_in[17];
    float* out = (float*)d_out;

    const int smemA = (4160 + 4352 + 5 * 64 + 512 + 2176) * 4;          // 46080 B
    const int smemB = (64 * P_WM1 + 256 * P_WM2 + 64 * P_WS + 256 + 4 * 64 +
                       2 * 32 * P_Z + 32 * P_H + 512) * 4;

    cudaFuncSetAttribute(kernelA, cudaFuncAttributeMaxDynamicSharedMemorySize, smemA);
    cudaFuncSetAttribute(kernelB, cudaFuncAttributeMaxDynamicSharedMemorySize, smemB);

    kernelA<<<592, 256, smemA>>>(u, x, Wk, bk, Wq, bq, Wv, bv, g1, be1);
    kernelB<<<148, 512, smemB>>>(x, Wm1, bm1, Wm2, bm2, g2, be2, Ws, bs, out);
}

// round 8
// speedup vs baseline: 2.0768x; 1.2014x over previous
#include <cuda_runtime.h>
#include <math.h>
#include <stdint.h>

#define FULLMASK 0xffffffffu

constexpr int Bb = 8;
constexpr int Nn = 7168;
constexpr int Uu = 49152;
constexpr int Cc = 64;

// scratch buffers
__device__ float g_z1[Bb * Nn * Cc];     // post-LN1 attention output
__device__ float gM[64 * 264];           // folded W-projection matrix (tf32 values)
__device__ float gC[264];                // folded bias row

__device__ __forceinline__ float warp_sum(float v) {
#pragma unroll
    for (int off = 16; off; off >>= 1) v += __shfl_xor_sync(FULLMASK, v, off);
    return v;
}

__device__ __forceinline__ float dot4(float4 a, float4 b, float acc) {
    acc = fmaf(a.x, b.x, acc);
    acc = fmaf(a.y, b.y, acc);
    acc = fmaf(a.z, b.z, acc);
    acc = fmaf(a.w, b.w, acc);
    return acc;
}

__device__ __forceinline__ float to_tf32(float x) {
    uint32_t r;
    asm("cvt.rna.tf32.f32 %0, %1;" : "=r"(r) : "f"(x));
    return __uint_as_float(r);
}

__device__ __forceinline__ void mma_tf32(float c[4],
    uint32_t a0, uint32_t a1, uint32_t a2, uint32_t a3,
    uint32_t b0, uint32_t b1)
{
    asm volatile(
        "mma.sync.aligned.m16n8k8.row.col.f32.tf32.tf32.f32 "
        "{%0,%1,%2,%3},{%4,%5,%6,%7},{%8,%9},{%0,%1,%2,%3};\n"
        : "+f"(c[0]), "+f"(c[1]), "+f"(c[2]), "+f"(c[3])
        : "r"(a0), "r"(a1), "r"(a2), "r"(a3), "r"(b0), "r"(b1));
}

// ---------------------------------------------------------------------------
// Kernel M: fold Wq/Wk/bq/bk (+scale 1/8) into gM[64x264], gC[264]
//   col = g*64+in  (g=0..3, in=0..63): w-vector columns
//   col = 256+g               : bkq columns
//   col = 260..263            : zero pad
// ---------------------------------------------------------------------------
extern "C" __global__ void kernelM(
    const float* __restrict__ Wk, const float* __restrict__ bk,
    const float* __restrict__ Wq, const float* __restrict__ bq)
{
    int idx = blockIdx.x * 256 + threadIdx.x;
    if (idx < 64 * 264) {
        int j = idx / 264, col = idx % 264;
        float acc = 0.f;
        if (col < 256) {
            int g = col >> 6, in = col & 63;
#pragma unroll
            for (int oo = 0; oo < 16; oo++) {
                int oc = g * 16 + oo;
                acc += Wq[j * 64 + oc] * Wk[in * 64 + oc];
            }
        } else if (col < 260) {
            int g = col - 256;
#pragma unroll
            for (int oo = 0; oo < 16; oo++) {
                int oc = g * 16 + oo;
                acc += Wq[j * 64 + oc] * bk[oc];
            }
        }
        gM[idx] = to_tf32(0.125f * acc);
    } else if (idx < 64 * 264 + 264) {
        int col = idx - 64 * 264;
        float acc = 0.f;
        if (col < 256) {
            int g = col >> 6, in = col & 63;
#pragma unroll
            for (int oo = 0; oo < 16; oo++) {
                int oc = g * 16 + oo;
                acc += bq[oc] * Wk[in * 64 + oc];
            }
        } else if (col < 260) {
            int g = col - 256;
#pragma unroll
            for (int oo = 0; oo < 16; oo++) {
                int oc = g * 16 + oo;
                acc += bq[oc] * bk[oc];
            }
        }
        gC[col] = 0.125f * acc;
    }
}

// ---------------------------------------------------------------------------
// Kernel A attention epilogue: one token, warp-wide
// ---------------------------------------------------------------------------
template <int TO>
__device__ __forceinline__ void attn_tok(
    const float* __restrict__ u,
    const float* sWt, const float* sWvT,
    const float* sbv, const float* sg1, const float* sbe1,
    float* myLog, float* myUb, int b, int n, int ltok, int l)
{
    int t, S0, S1;
    if (TO == 4)      { t = n;        S0 = 0;     S1 = 24576; }
    else if (TO == 8) { t = n - 4096; S0 = 8192;  S1 = 32768; }
    else              { t = n - 6144; S0 = 16384; S1 = 40960; }
    int cidx = t * TO;
    int base = (cidx < 8192) ? (S0 + cidx) : (S1 + cidx - 8192);
    const float* uptr = u + ((size_t)b * Uu + base) * Cc;

    // w vectors + bkq from the per-tile GEMM result
    const float* wrow = sWt + ltok * 265;
    float wg0[4], wg1[4];
#pragma unroll
    for (int g = 0; g < 4; g++) {
        wg0[g] = wrow[g * 64 + l];
        wg1[g] = wrow[g * 64 + 32 + l];
    }
    float bk_sel = (l < 4) ? wrow[256 + l] : 0.f;

    // load the TO contiguous u rows
    float ur0[TO], ur1[TO];
#pragma unroll
    for (int r = 0; r < TO; r++) {
        ur0[r] = uptr[r * 64 + l];
        ur1[r] = uptr[r * 64 + l + 32];
    }

    // logits: 6-shfl multi-value reduction
#pragma unroll
    for (int r = 0; r < TO; r++) {
        float p0 = ur0[r] * wg0[0] + ur1[r] * wg1[0];
        float p1 = ur0[r] * wg0[1] + ur1[r] * wg1[1];
        float p2 = ur0[r] * wg0[2] + ur1[r] * wg1[2];
        float p3 = ur0[r] * wg0[3] + ur1[r] * wg1[3];
        float t0 = (l & 1) ? p0 : p1;
        float r0 = __shfl_xor_sync(FULLMASK, t0, 1);
        float a = ((l & 1) ? p1 : p0) + r0;
        float t1 = (l & 1) ? p2 : p3;
        float r1 = __shfl_xor_sync(FULLMASK, t1, 1);
        float bb = ((l & 1) ? p3 : p2) + r1;
        float t2 = (l & 2) ? a : bb;
        float r2 = __shfl_xor_sync(FULLMASK, t2, 2);
        float c = ((l & 2) ? bb : a) + r2;
        c += __shfl_xor_sync(FULLMASK, c, 4);
        c += __shfl_xor_sync(FULLMASK, c, 8);
        c += __shfl_xor_sync(FULLMASK, c, 16);
        if (l < 4) myLog[r * 4 + l] = c + bk_sel;
    }
    __syncwarp();

    // softmax over r, one group per lane (lanes 0..3)
    if (l < 4) {
        float m = -1e30f;
#pragma unroll
        for (int r = 0; r < TO; r++) m = fmaxf(m, myLog[r * 4 + l]);
        float s = 0.f;
#pragma unroll
        for (int r = 0; r < TO; r++) {
            float e = __expf(myLog[r * 4 + l] - m);
            s += e;
            myLog[r * 4 + l] = e;
        }
        float inv = 1.f / s;
#pragma unroll
        for (int r = 0; r < TO; r++) myLog[r * 4 + l] *= inv;
    }
    __syncwarp();

    // ubar[g] = sum_r p[r][g] * u_r
    float ub0[4] = {0.f, 0.f, 0.f, 0.f}, ub1[4] = {0.f, 0.f, 0.f, 0.f};
#pragma unroll
    for (int r = 0; r < TO; r++) {
        float pg0 = myLog[r * 4 + 0], pg1 = myLog[r * 4 + 1];
        float pg2 = myLog[r * 4 + 2], pg3 = myLog[r * 4 + 3];
        ub0[0] += pg0 * ur0[r]; ub1[0] += pg0 * ur1[r];
        ub0[1] += pg1 * ur0[r]; ub1[1] += pg1 * ur1[r];
        ub0[2] += pg2 * ur0[r]; ub1[2] += pg2 * ur1[r];
        ub0[3] += pg3 * ur0[r]; ub1[3] += pg3 * ur1[r];
    }

    __syncwarp();
#pragma unroll
    for (int g = 0; g < 4; g++) {
        myUb[g * 68 + l]      = ub0[g];
        myUb[g * 68 + 32 + l] = ub1[g];
    }
    __syncwarp();

    const int ga = l >> 4;
    const int gb = ga + 2;
    float av0 = sbv[l], av1 = sbv[l + 32];
#pragma unroll
    for (int in = 0; in < 64; in += 4) {
        float4 ua = *(const float4*)&myUb[ga * 68 + in];
        float4 ub = *(const float4*)&myUb[gb * 68 + in];
        float4 wa = *(const float4*)&sWvT[l * 68 + in];
        float4 wb = *(const float4*)&sWvT[(l + 32) * 68 + in];
        av0 = dot4(ua, wa, av0);
        av1 = dot4(ub, wb, av1);
    }

    // LN1 and write to scratch
    float mean = warp_sum(av0 + av1) * (1.f / 64.f);
    float d0 = av0 - mean, d1 = av1 - mean;
    float var = warp_sum(d0 * d0 + d1 * d1) * (1.f / 64.f);
    float inv = rsqrtf(var + 1e-5f);
    size_t o = ((size_t)b * Nn + n) * Cc;
    g_z1[o + l]      = d0 * inv * sg1[l]      + sbe1[l];
    g_z1[o + l + 32] = d1 * inv * sg1[l + 32] + sbe1[l + 32];
}

// ---------------------------------------------------------------------------
// Kernel A: per 32-token tile — MMA W-GEMM (X @ gM) then warp attention
// ---------------------------------------------------------------------------
extern "C" __global__ void __launch_bounds__(256, 3)
kernelA(const float* __restrict__ u, const float* __restrict__ x,
        const float* __restrict__ Wv, const float* __restrict__ bv,
        const float* __restrict__ g1, const float* __restrict__ be1)
{
    extern __shared__ float sm[];
    float* sWvT = sm;                 // 64*68 = 4352
    float* sGC  = sWvT + 4352;        // 264
    float* sbv  = sGC + 264;          // 64
    float* sg1  = sbv + 64;
    float* sbe1 = sg1 + 64;
    float* sX   = sbe1 + 64;          // 32*68 = 2176
    float* sWt  = sX + 2176;          // 32*265 = 8480
    float* sLog = sWt + 8480;         // 8*64 = 512
    float* sUb  = sLog + 512;         // 8*272 = 2176

    int tid = threadIdx.x;
    for (int i = tid; i < 4096; i += 256) {
        int in = i >> 6, oc = i & 63;
        sWvT[oc * 68 + in] = Wv[i];
    }
    for (int i = tid; i < 264; i += 256) sGC[i] = gC[i];
    if (tid < 64) { sbv[tid] = bv[tid]; sg1[tid] = g1[tid]; sbe1[tid] = be1[tid]; }
    __syncthreads();

    const int warp = tid >> 5, l = tid & 31;
    const int wm = warp >> 2, wn = warp & 3;     // 2 m-tiles x 4 n-groups
    const int lq = l >> 2, lr = l & 3;
    float* myLog = sLog + warp * 64;
    float* myUb  = sUb + warp * 272;

    for (int blk = blockIdx.x; blk < 1792; blk += gridDim.x) {
        int b = blk / 224;
        int n_base = (blk % 224) * 32;

        // load X tile -> sX (tf32-rounded), 8 floats per thread
        {
            int row = tid >> 3, seg = (tid & 7) * 8;
            const float* xp = x + ((size_t)b * Nn + n_base + row) * 64 + seg;
            float4 a4 = *(const float4*)xp;
            float4 b4 = *(const float4*)(xp + 4);
            a4.x = to_tf32(a4.x); a4.y = to_tf32(a4.y); a4.z = to_tf32(a4.z); a4.w = to_tf32(a4.w);
            b4.x = to_tf32(b4.x); b4.y = to_tf32(b4.y); b4.z = to_tf32(b4.z); b4.w = to_tf32(b4.w);
            *(float4*)&sX[row * 68 + seg] = a4;
            *(float4*)&sX[row * 68 + seg + 4] = b4;
        }
        __syncthreads();

        // GEMM-W: Wt[32x264] = X @ gM (+gC). B-frags read from global gM.
        {
            float c[9][4];
#pragma unroll
            for (int nt = 0; nt < 9; nt++)
#pragma unroll
                for (int j = 0; j < 4; j++) c[nt][j] = 0.f;

            const float* A1 = sX + (wm * 16 + lq) * 68 + lr;
#pragma unroll
            for (int k0 = 0; k0 < 64; k0 += 8) {
                uint32_t a0 = __float_as_uint(A1[k0]);
                uint32_t a1 = __float_as_uint(A1[k0 + 8 * 68]);
                uint32_t a2 = __float_as_uint(A1[k0 + 4]);
                uint32_t a3 = __float_as_uint(A1[k0 + 8 * 68 + 4]);
                const float* Bp = gM + (k0 + lr) * 264 + lq;
#pragma unroll
                for (int nt = 0; nt < 8; nt++) {
                    int cb = wn * 64 + nt * 8;
                    uint32_t b0 = __float_as_uint(Bp[cb]);
                    uint32_t b1 = __float_as_uint(Bp[4 * 264 + cb]);
                    mma_tf32(c[nt], a0, a1, a2, a3, b0, b1);
                }
                if (wn == 0) {
                    uint32_t b0 = __float_as_uint(Bp[256]);
                    uint32_t b1 = __float_as_uint(Bp[4 * 264 + 256]);
                    mma_tf32(c[8], a0, a1, a2, a3, b0, b1);
                }
            }
            int r0 = wm * 16 + lq, r1 = r0 + 8;
#pragma unroll
            for (int nt = 0; nt < 8; nt++) {
                int col = wn * 64 + nt * 8 + lr * 2;
                sWt[r0 * 265 + col]     = c[nt][0] + sGC[col];
                sWt[r0 * 265 + col + 1] = c[nt][1] + sGC[col + 1];
                sWt[r1 * 265 + col]     = c[nt][2] + sGC[col];
                sWt[r1 * 265 + col + 1] = c[nt][3] + sGC[col + 1];
            }
            if (wn == 0) {
                int col = 256 + lr * 2;
                sWt[r0 * 265 + col]     = c[8][0] + sGC[col];
                sWt[r0 * 265 + col + 1] = c[8][1] + sGC[col + 1];
                sWt[r1 * 265 + col]     = c[8][2] + sGC[col];
                sWt[r1 * 265 + col + 1] = c[8][3] + sGC[col + 1];
            }
        }
        __syncthreads();

        // attention: 4 tokens per warp
#pragma unroll
        for (int tt = 0; tt < 4; tt++) {
            int ltok = warp * 4 + tt;
            int n = n_base + ltok;
            if (n_base < 4096)
                attn_tok<4>(u, sWt, sWvT, sbv, sg1, sbe1, myLog, myUb, b, n, ltok, l);
            else if (n_base < 6144)
                attn_tok<8>(u, sWt, sWvT, sbv, sg1, sbe1, myLog, myUb, b, n, ltok, l);
            else
                attn_tok<16>(u, sWt, sWvT, sbv, sg1, sbe1, myLog, myUb, b, n, ltok, l);
        }
        __syncthreads();
    }
}

// ---------------------------------------------------------------------------
// Kernel B (tf32 tensor cores): MLP + LN2 + shortcut  (unchanged from R5)
// ---------------------------------------------------------------------------
constexpr int P_WM1 = 264;
constexpr int P_WM2 = 72;
constexpr int P_WS  = 72;
constexpr int P_Z   = 68;
constexpr int P_H   = 260;

extern "C" __global__ void __launch_bounds__(512)
kernelB(const float* __restrict__ x,
        const float* __restrict__ Wm1, const float* __restrict__ bm1,
        const float* __restrict__ Wm2, const float* __restrict__ bm2,
        const float* __restrict__ g2,  const float* __restrict__ be2,
        const float* __restrict__ Ws,  const float* __restrict__ bs,
        float* __restrict__ out)
{
    extern __shared__ float sm[];
    float* sWm1f = sm;
    float* sWm2f = sWm1f + 64 * P_WM1;
    float* sWsf  = sWm2f + 256 * P_WM2;
    float* sbm1  = sWsf + 64 * P_WS;
    float* sbm2  = sbm1 + 256;
    float* sg2   = sbm2 + 64;
    float* sbe2  = sg2 + 64;
    float* sbs   = sbe2 + 64;
    float* sZ    = sbs + 64;
    float* sX    = sZ + 32 * P_Z;
    float* sH    = sX + 32 * P_Z;
    float* sRedS = sH + 32 * P_H;
    float* sRedQ = sRedS + 256;

    int tid = threadIdx.x;
    for (int i = tid; i < 64 * 256; i += 512) {
        int k = i >> 8, n = i & 255;
        sWm1f[k * P_WM1 + n] = to_tf32(Wm1[i]);
    }
    for (int i = tid; i < 256 * 64; i += 512) {
        int k = i >> 6, n = i & 63;
        sWm2f[k * P_WM2 + n] = to_tf32(Wm2[i]);
    }
    for (int i = tid; i < 64 * 64; i += 512) {
        int k = i >> 6, n = i & 63;
        sWsf[k * P_WS + n] = to_tf32(Ws[i]);
    }
    if (tid < 256) sbm1[tid] = bm1[tid];
    if (tid < 64) { sbm2[tid] = bm2[tid]; sg2[tid] = g2[tid]; sbe2[tid] = be2[tid]; sbs[tid] = bs[tid]; }
    __syncthreads();

    const int warp = tid >> 5, lane = tid & 31;
    const int wm = warp >> 3, wn = warp & 7;
    const int lq = lane >> 2, lr = lane & 3;
    const int row_lo = wm * 16 + lq;
    const int row_hi = row_lo + 8;
    const int NTILES = Bb * Nn / 32;

    for (int tile = blockIdx.x; tile < NTILES; tile += gridDim.x) {
        size_t base = (size_t)tile * 32 * 64;
        {
            int row = tid >> 4, seg = (tid & 15) * 4;
            float4 z4 = *(const float4*)(g_z1 + base + row * 64 + seg);
            float4 x4 = *(const float4*)(x + base + row * 64 + seg);
            z4.x = to_tf32(z4.x); z4.y = to_tf32(z4.y); z4.z = to_tf32(z4.z); z4.w = to_tf32(z4.w);
            x4.x = to_tf32(x4.x); x4.y = to_tf32(x4.y); x4.z = to_tf32(x4.z); x4.w = to_tf32(x4.w);
            *(float4*)&sZ[row * P_Z + seg] = z4;
            *(float4*)&sX[row * P_Z + seg] = x4;
        }
        __syncthreads();

        float c[4][4];
#pragma unroll
        for (int nt = 0; nt < 4; nt++)
#pragma unroll
            for (int j = 0; j < 4; j++) c[nt][j] = 0.f;

        const float* A1 = sZ + (wm * 16 + lq) * P_Z + lr;
#pragma unroll
        for (int k0 = 0; k0 < 64; k0 += 8) {
            uint32_t a0 = __float_as_uint(A1[k0]);
            uint32_t a1 = __float_as_uint(A1[k0 + 8 * P_Z]);
            uint32_t a2 = __float_as_uint(A1[k0 + 4]);
            uint32_t a3 = __float_as_uint(A1[k0 + 8 * P_Z + 4]);
            const float* B1 = sWm1f + (k0 + lr) * P_WM1 + wn * 32 + lq;
#pragma unroll
            for (int nt = 0; nt < 4; nt++) {
                uint32_t b0 = __float_as_uint(B1[nt * 8]);
                uint32_t b1 = __float_as_uint(B1[4 * P_WM1 + nt * 8]);
                mma_tf32(c[nt], a0, a1, a2, a3, b0, b1);
            }
        }
#pragma unroll
        for (int nt = 0; nt < 4; nt++) {
            int col = wn * 32 + nt * 8 + lr * 2;
            float v0 = c[nt][0] + sbm1[col];
            float v1 = c[nt][1] + sbm1[col + 1];
            float v2 = c[nt][2] + sbm1[col];
            float v3 = c[nt][3] + sbm1[col + 1];
            sH[row_lo * P_H + col]     = to_tf32(v0 * 0.5f * (1.f + erff(v0 * 0.70710678118654752f)));
            sH[row_lo * P_H + col + 1] = to_tf32(v1 * 0.5f * (1.f + erff(v1 * 0.70710678118654752f)));
            sH[row_hi * P_H + col]     = to_tf32(v2 * 0.5f * (1.f + erff(v2 * 0.70710678118654752f)));
            sH[row_hi * P_H + col + 1] = to_tf32(v3 * 0.5f * (1.f + erff(v3 * 0.70710678118654752f)));
        }
        __syncthreads();

        float o[4] = {0.f, 0.f, 0.f, 0.f};
        float s[4] = {0.f, 0.f, 0.f, 0.f};
        const float* A2 = sH + (wm * 16 + lq) * P_H + lr;
        const float* B2 = sWm2f + lr * P_WM2 + wn * 8 + lq;
#pragma unroll
        for (int k0 = 0; k0 < 256; k0 += 8) {
            uint32_t a0 = __float_as_uint(A2[k0]);
            uint32_t a1 = __float_as_uint(A2[k0 + 8 * P_H]);
            uint32_t a2 = __float_as_uint(A2[k0 + 4]);
            uint32_t a3 = __float_as_uint(A2[k0 + 8 * P_H + 4]);
            uint32_t b0 = __float_as_uint(B2[k0 * P_WM2]);
            uint32_t b1 = __float_as_uint(B2[(k0 + 4) * P_WM2]);
            mma_tf32(o, a0, a1, a2, a3, b0, b1);
        }
        const float* A3 = sX + (wm * 16 + lq) * P_Z + lr;
        const float* B3 = sWsf + lr * P_WS + wn * 8 + lq;
#pragma unroll
        for (int k0 = 0; k0 < 64; k0 += 8) {
            uint32_t a0 = __float_as_uint(A3[k0]);
            uint32_t a1 = __float_as_uint(A3[k0 + 8 * P_Z]);
            uint32_t a2 = __float_as_uint(A3[k0 + 4]);
            uint32_t a3 = __float_as_uint(A3[k0 + 8 * P_Z + 4]);
            uint32_t b0 = __float_as_uint(B3[k0 * P_WS]);
            uint32_t b1 = __float_as_uint(B3[(k0 + 4) * P_WS]);
            mma_tf32(s, a0, a1, a2, a3, b0, b1);
        }

        int col = wn * 8 + lr * 2;
        o[0] += sbm2[col]; o[1] += sbm2[col + 1];
        o[2] += sbm2[col]; o[3] += sbm2[col + 1];

        float slo = o[0] + o[1], shi = o[2] + o[3];
        float qlo = o[0] * o[0] + o[1] * o[1], qhi = o[2] * o[2] + o[3] * o[3];
#pragma unroll
        for (int off = 1; off <= 2; off <<= 1) {
            slo += __shfl_xor_sync(FULLMASK, slo, off);
            shi += __shfl_xor_sync(FULLMASK, shi, off);
            qlo += __shfl_xor_sync(FULLMASK, qlo, off);
            qhi += __shfl_xor_sync(FULLMASK, qhi, off);
        }
        if (lr == 0) {
            sRedS[row_lo * 8 + wn] = slo;  sRedQ[row_lo * 8 + wn] = qlo;
            sRedS[row_hi * 8 + wn] = shi;  sRedQ[row_hi * 8 + wn] = qhi;
        }
        __syncthreads();

        float ms_lo = 0.f, mq_lo = 0.f, ms_hi = 0.f, mq_hi = 0.f;
#pragma unroll
        for (int j = 0; j < 8; j++) {
            ms_lo += sRedS[row_lo * 8 + j];  mq_lo += sRedQ[row_lo * 8 + j];
            ms_hi += sRedS[row_hi * 8 + j];  mq_hi += sRedQ[row_hi * 8 + j];
        }
        float mean_lo = ms_lo * (1.f / 64.f);
        float mean_hi = ms_hi * (1.f / 64.f);
        float inv_lo = rsqrtf(mq_lo * (1.f / 64.f) - mean_lo * mean_lo + 1e-5f);
        float inv_hi = rsqrtf(mq_hi * (1.f / 64.f) - mean_hi * mean_hi + 1e-5f);

        float g0 = sg2[col], g1v = sg2[col + 1];
        float e0 = sbe2[col], e1 = sbe2[col + 1];
        float bs0 = sbs[col], bs1 = sbs[col + 1];

        float2 r_lo, r_hi;
        r_lo.x = (o[0] - mean_lo) * inv_lo * g0  + e0 + s[0] + bs0;
        r_lo.y = (o[1] - mean_lo) * inv_lo * g1v + e1 + s[1] + bs1;
        r_hi.x = (o[2] - mean_hi) * inv_hi * g0  + e0 + s[2] + bs0;
        r_hi.y = (o[3] - mean_hi) * inv_hi * g1v + e1 + s[3] + bs1;

        *(float2*)(out + base + (size_t)row_lo * 64 + col) = r_lo;
        *(float2*)(out + base + (size_t)row_hi * 64 + col) = r_hi;
        __syncthreads();
    }
}

// ---------------------------------------------------------------------------
extern "C" void kernel_launch(void* const* d_in, const int* in_sizes, int n_in,
                              void* d_out, int out_size)
{
    const float* u   = (const float*)d_in[0];
    const float* x   = (const float*)d_in[1];
    const float* Wk  = (const float*)d_in[2];
    const float* bk  = (const float*)d_in[3];
    const float* Wq  = (const float*)d_in[4];
    const float* bq  = (const float*)d_in[5];
    const float* Wv  = (const float*)d_in[6];
    const float* bv  = (const float*)d_in[7];
    const float* g1  = (const float*)d_in[8];
    const float* be1 = (const float*)d_in[9];
    const float* Wm1 = (const float*)d_in[10];
    const float* bm1 = (const float*)d_in[11];
    const float* Wm2 = (const float*)d_in[12];
    const float* bm2 = (const float*)d_in[13];
    const float* g2  = (const float*)d_in[14];
    const float* be2 = (const float*)d_in[15];
    const float* Ws  = (const float*)d_in[16];
    const float* bs  = (const float*)d_in[17];
    float* out = (float*)d_out;

    const int smemA = (4352 + 264 + 3 * 64 + 2176 + 8480 + 512 + 2176) * 4;  // 72608 B
    const int smemB = (64 * P_WM1 + 256 * P_WM2 + 64 * P_WS + 256 + 4 * 64 +
                       2 * 32 * P_Z + 32 * P_H + 512) * 4;

    cudaFuncSetAttribute(kernelA, cudaFuncAttributeMaxDynamicSharedMemorySize, smemA);
    cudaFuncSetAttribute(kernelB, cudaFuncAttributeMaxDynamicSharedMemorySize, smemB);

    kernelM<<<68, 256>>>(Wk, bk, Wq, bq);
    kernelA<<<444, 256, smemA>>>(u, x, Wv, bv, g1, be1);
    kernelB<<<148, 512, smemB>>>(x, Wm1, bm1, Wm2, bm2, g2, be2, Ws, bs, out);
}

// round 9
// speedup vs baseline: 2.2788x; 1.0972x over previous
#include <cuda_runtime.h>
#include <math.h>
#include <stdint.h>

#define FULLMASK 0xffffffffu

constexpr int Bb = 8;
constexpr int Nn = 7168;
constexpr int Uu = 49152;
constexpr int Cc = 64;

// scratch buffers
__device__ float g_z1[Bb * Nn * Cc];     // post-LN1 attention output
__device__ float gM[64 * 264];           // folded W-projection matrix (tf32 values)
__device__ float gC[264];                // folded bias row
__device__ float gWv[256 * 72];          // block-diagonal V matrix (tf32), row=g*64+in

__device__ __forceinline__ float to_tf32(float x) {
    uint32_t r;
    asm("cvt.rna.tf32.f32 %0, %1;" : "=r"(r) : "f"(x));
    return __uint_as_float(r);
}

__device__ __forceinline__ void mma_tf32(float c[4],
    uint32_t a0, uint32_t a1, uint32_t a2, uint32_t a3,
    uint32_t b0, uint32_t b1)
{
    asm volatile(
        "mma.sync.aligned.m16n8k8.row.col.f32.tf32.tf32.f32 "
        "{%0,%1,%2,%3},{%4,%5,%6,%7},{%8,%9},{%0,%1,%2,%3};\n"
        : "+f"(c[0]), "+f"(c[1]), "+f"(c[2]), "+f"(c[3])
        : "r"(a0), "r"(a1), "r"(a2), "r"(a3), "r"(b0), "r"(b1));
}

// ---------------------------------------------------------------------------
// Kernel M: fold Wq/Wk/bq/bk (+scale) into gM/gC; build block-diagonal gWv
// ---------------------------------------------------------------------------
extern "C" __global__ void kernelM(
    const float* __restrict__ Wk, const float* __restrict__ bk,
    const float* __restrict__ Wq, const float* __restrict__ bq,
    const float* __restrict__ Wv)
{
    int idx = blockIdx.x * 256 + threadIdx.x;
    if (idx < 64 * 264) {
        int j = idx / 264, col = idx % 264;
        float acc = 0.f;
        if (col < 256) {
            int g = col >> 6, in = col & 63;
#pragma unroll
            for (int oo = 0; oo < 16; oo++) {
                int oc = g * 16 + oo;
                acc += Wq[j * 64 + oc] * Wk[in * 64 + oc];
            }
        } else if (col < 260) {
            int g = col - 256;
#pragma unroll
            for (int oo = 0; oo < 16; oo++) {
                int oc = g * 16 + oo;
                acc += Wq[j * 64 + oc] * bk[oc];
            }
        }
        gM[idx] = to_tf32(0.125f * acc);
    } else if (idx < 64 * 264 + 264) {
        int col = idx - 64 * 264;
        float acc = 0.f;
        if (col < 256) {
            int g = col >> 6, in = col & 63;
#pragma unroll
            for (int oo = 0; oo < 16; oo++) {
                int oc = g * 16 + oo;
                acc += bq[oc] * Wk[in * 64 + oc];
            }
        } else if (col < 260) {
            int g = col - 256;
#pragma unroll
            for (int oo = 0; oo < 16; oo++) {
                int oc = g * 16 + oo;
                acc += bq[oc] * bk[oc];
            }
        }
        gC[col] = 0.125f * acc;
    } else if (idx < 64 * 264 + 264 + 256 * 72) {
        int j = idx - (64 * 264 + 264);
        int row = j / 72, oc = j % 72;
        float v = 0.f;
        if (oc < 64) {
            int g = row >> 6, in = row & 63;
            if ((oc >> 4) == g) v = Wv[in * 64 + oc];
        }
        gWv[row * 72 + oc] = to_tf32(v);
    }
}

// ---------------------------------------------------------------------------
// Kernel A attention epilogue for one token: logits/softmax/ubar -> sWt row
// ---------------------------------------------------------------------------
template <int TO>
__device__ __forceinline__ void attn_tok(
    const float* __restrict__ u,
    float* sWt, float* myLog, int b, int n, int ltok, int l)
{
    int t, S0, S1;
    if (TO == 4)      { t = n;        S0 = 0;     S1 = 24576; }
    else if (TO == 8) { t = n - 4096; S0 = 8192;  S1 = 32768; }
    else              { t = n - 6144; S0 = 16384; S1 = 40960; }
    int cidx = t * TO;
    int base = (cidx < 8192) ? (S0 + cidx) : (S1 + cidx - 8192);
    const float* uptr = u + ((size_t)b * Uu + base) * Cc;

    // w vectors + bkq from the per-tile GEMM result (read fully before overwrite)
    float* wrow = sWt + ltok * 265;
    float wg0[4], wg1[4];
#pragma unroll
    for (int g = 0; g < 4; g++) {
        wg0[g] = wrow[g * 64 + l];
        wg1[g] = wrow[g * 64 + 32 + l];
    }
    float bk_sel = (l < 4) ? wrow[256 + l] : 0.f;

    // load the TO contiguous u rows
    float ur0[TO], ur1[TO];
#pragma unroll
    for (int r = 0; r < TO; r++) {
        ur0[r] = uptr[r * 64 + l];
        ur1[r] = uptr[r * 64 + l + 32];
    }

    // logits: 6-shfl multi-value reduction
#pragma unroll
    for (int r = 0; r < TO; r++) {
        float p0 = ur0[r] * wg0[0] + ur1[r] * wg1[0];
        float p1 = ur0[r] * wg0[1] + ur1[r] * wg1[1];
        float p2 = ur0[r] * wg0[2] + ur1[r] * wg1[2];
        float p3 = ur0[r] * wg0[3] + ur1[r] * wg1[3];
        float t0 = (l & 1) ? p0 : p1;
        float r0 = __shfl_xor_sync(FULLMASK, t0, 1);
        float a = ((l & 1) ? p1 : p0) + r0;
        float t1 = (l & 1) ? p2 : p3;
        float r1 = __shfl_xor_sync(FULLMASK, t1, 1);
        float bb = ((l & 1) ? p3 : p2) + r1;
        float t2 = (l & 2) ? a : bb;
        float r2 = __shfl_xor_sync(FULLMASK, t2, 2);
        float c = ((l & 2) ? bb : a) + r2;
        c += __shfl_xor_sync(FULLMASK, c, 4);
        c += __shfl_xor_sync(FULLMASK, c, 8);
        c += __shfl_xor_sync(FULLMASK, c, 16);
        if (l < 4) myLog[r * 4 + l] = c + bk_sel;
    }
    __syncwarp();

    // softmax over r, one group per lane (lanes 0..3)
    if (l < 4) {
        float m = -1e30f;
#pragma unroll
        for (int r = 0; r < TO; r++) m = fmaxf(m, myLog[r * 4 + l]);
        float s = 0.f;
#pragma unroll
        for (int r = 0; r < TO; r++) {
            float e = __expf(myLog[r * 4 + l] - m);
            s += e;
            myLog[r * 4 + l] = e;
        }
        float inv = 1.f / s;
#pragma unroll
        for (int r = 0; r < TO; r++) myLog[r * 4 + l] *= inv;
    }
    __syncwarp();

    // ubar[g] = sum_r p[r][g] * u_r
    float ub0[4] = {0.f, 0.f, 0.f, 0.f}, ub1[4] = {0.f, 0.f, 0.f, 0.f};
#pragma unroll
    for (int r = 0; r < TO; r++) {
        float pg0 = myLog[r * 4 + 0], pg1 = myLog[r * 4 + 1];
        float pg2 = myLog[r * 4 + 2], pg3 = myLog[r * 4 + 3];
        ub0[0] += pg0 * ur0[r]; ub1[0] += pg0 * ur1[r];
        ub0[1] += pg1 * ur0[r]; ub1[1] += pg1 * ur1[r];
        ub0[2] += pg2 * ur0[r]; ub1[2] += pg2 * ur1[r];
        ub0[3] += pg3 * ur0[r]; ub1[3] += pg3 * ur1[r];
    }

    // overwrite this token's sWt row with tf32 ubar (cols g*64 + ch)
#pragma unroll
    for (int g = 0; g < 4; g++) {
        wrow[g * 64 + l]      = to_tf32(ub0[g]);
        wrow[g * 64 + 32 + l] = to_tf32(ub1[g]);
    }
}

// ---------------------------------------------------------------------------
// Kernel A: per 32-token tile — W-GEMM, warp attention, V-GEMM + LN1
// ---------------------------------------------------------------------------
extern "C" __global__ void __launch_bounds__(256, 3)
kernelA(const float* __restrict__ u, const float* __restrict__ x,
        const float* __restrict__ bv,
        const float* __restrict__ g1, const float* __restrict__ be1)
{
    extern __shared__ float sm[];
    float* sGC   = sm;              // 264
    float* sbv   = sGC + 264;       // 64
    float* sg1   = sbv + 64;        // 64
    float* sbe1  = sg1 + 64;        // 64
    float* sX    = sbe1 + 64;       // 32*68 = 2176
    float* sWt   = sX + 2176;       // 32*265 = 8480 (w-vectors, then ubar)
    float* sLog  = sWt + 8480;      // 8*64 = 512
    float* sRedS = sLog + 512;      // 32*4 = 128
    float* sRedQ = sRedS + 128;     // 128

    int tid = threadIdx.x;
    for (int i = tid; i < 264; i += 256) sGC[i] = gC[i];
    if (tid < 64) { sbv[tid] = bv[tid]; sg1[tid] = g1[tid]; sbe1[tid] = be1[tid]; }
    __syncthreads();

    const int warp = tid >> 5, l = tid & 31;
    const int wm = warp >> 2, wn = warp & 3;     // 2 m-tiles x 4 n-groups
    const int lq = l >> 2, lr = l & 3;
    float* myLog = sLog + warp * 64;

    for (int blk = blockIdx.x; blk < 1792; blk += gridDim.x) {
        int b = blk / 224;
        int n_base = (blk % 224) * 32;

        // load X tile -> sX (tf32-rounded), 8 floats per thread
        {
            int row = tid >> 3, seg = (tid & 7) * 8;
            const float* xp = x + ((size_t)b * Nn + n_base + row) * 64 + seg;
            float4 a4 = *(const float4*)xp;
            float4 b4 = *(const float4*)(xp + 4);
            a4.x = to_tf32(a4.x); a4.y = to_tf32(a4.y); a4.z = to_tf32(a4.z); a4.w = to_tf32(a4.w);
            b4.x = to_tf32(b4.x); b4.y = to_tf32(b4.y); b4.z = to_tf32(b4.z); b4.w = to_tf32(b4.w);
            *(float4*)&sX[row * 68 + seg] = a4;
            *(float4*)&sX[row * 68 + seg + 4] = b4;
        }
        __syncthreads();

        // GEMM-W: Wt[32x264] = X @ gM (+gC). B-frags read from global gM.
        {
            float c[9][4];
#pragma unroll
            for (int nt = 0; nt < 9; nt++)
#pragma unroll
                for (int j = 0; j < 4; j++) c[nt][j] = 0.f;

            const float* A1 = sX + (wm * 16 + lq) * 68 + lr;
#pragma unroll
            for (int k0 = 0; k0 < 64; k0 += 8) {
                uint32_t a0 = __float_as_uint(A1[k0]);
                uint32_t a1 = __float_as_uint(A1[k0 + 8 * 68]);
                uint32_t a2 = __float_as_uint(A1[k0 + 4]);
                uint32_t a3 = __float_as_uint(A1[k0 + 8 * 68 + 4]);
                const float* Bp = gM + (k0 + lr) * 264 + lq;
#pragma unroll
                for (int nt = 0; nt < 8; nt++) {
                    int cb = wn * 64 + nt * 8;
                    uint32_t b0 = __float_as_uint(Bp[cb]);
                    uint32_t b1 = __float_as_uint(Bp[4 * 264 + cb]);
                    mma_tf32(c[nt], a0, a1, a2, a3, b0, b1);
                }
                if (wn == 0) {
                    uint32_t b0 = __float_as_uint(Bp[256]);
                    uint32_t b1 = __float_as_uint(Bp[4 * 264 + 256]);
                    mma_tf32(c[8], a0, a1, a2, a3, b0, b1);
                }
            }
            int r0 = wm * 16 + lq, r1 = r0 + 8;
#pragma unroll
            for (int nt = 0; nt < 8; nt++) {
                int col = wn * 64 + nt * 8 + lr * 2;
                sWt[r0 * 265 + col]     = c[nt][0] + sGC[col];
                sWt[r0 * 265 + col + 1] = c[nt][1] + sGC[col + 1];
                sWt[r1 * 265 + col]     = c[nt][2] + sGC[col];
                sWt[r1 * 265 + col + 1] = c[nt][3] + sGC[col + 1];
            }
            if (wn == 0) {
                int col = 256 + lr * 2;
                sWt[r0 * 265 + col]     = c[8][0] + sGC[col];
                sWt[r0 * 265 + col + 1] = c[8][1] + sGC[col + 1];
                sWt[r1 * 265 + col]     = c[8][2] + sGC[col];
                sWt[r1 * 265 + col + 1] = c[8][3] + sGC[col + 1];
            }
        }
        __syncthreads();

        // attention: 4 tokens per warp; each writes its ubar back into sWt
#pragma unroll
        for (int tt = 0; tt < 4; tt++) {
            int ltok = warp * 4 + tt;
            int n = n_base + ltok;
            if (n_base < 4096)
                attn_tok<4>(u, sWt, myLog, b, n, ltok, l);
            else if (n_base < 6144)
                attn_tok<8>(u, sWt, myLog, b, n, ltok, l);
            else
                attn_tok<16>(u, sWt, myLog, b, n, ltok, l);
        }
        __syncthreads();

        // V-GEMM: attv[32x64] = Ub[32x256] @ gWv (+bv); LN1 -> g_z1
        {
            float oA[2][4], oB[2][4];
#pragma unroll
            for (int nt = 0; nt < 2; nt++)
#pragma unroll
                for (int j = 0; j < 4; j++) { oA[nt][j] = 0.f; oB[nt][j] = 0.f; }

            const float* A = sWt + (wm * 16 + lq) * 265 + lr;
#pragma unroll
            for (int k0 = 0; k0 < 256; k0 += 16) {
                uint32_t a0 = __float_as_uint(A[k0]);
                uint32_t a1 = __float_as_uint(A[k0 + 8 * 265]);
                uint32_t a2 = __float_as_uint(A[k0 + 4]);
                uint32_t a3 = __float_as_uint(A[k0 + 8 * 265 + 4]);
                const float* Bp = gWv + (k0 + lr) * 72 + wn * 16 + lq;
#pragma unroll
                for (int nt = 0; nt < 2; nt++) {
                    uint32_t b0 = __float_as_uint(Bp[nt * 8]);
                    uint32_t b1 = __float_as_uint(Bp[4 * 72 + nt * 8]);
                    mma_tf32(oA[nt], a0, a1, a2, a3, b0, b1);
                }
                uint32_t c0 = __float_as_uint(A[k0 + 8]);
                uint32_t c1 = __float_as_uint(A[k0 + 8 + 8 * 265]);
                uint32_t c2 = __float_as_uint(A[k0 + 8 + 4]);
                uint32_t c3 = __float_as_uint(A[k0 + 8 + 8 * 265 + 4]);
                const float* Bq = gWv + (k0 + 8 + lr) * 72 + wn * 16 + lq;
#pragma unroll
                for (int nt = 0; nt < 2; nt++) {
                    uint32_t b0 = __float_as_uint(Bq[nt * 8]);
                    uint32_t b1 = __float_as_uint(Bq[4 * 72 + nt * 8]);
                    mma_tf32(oB[nt], c0, c1, c2, c3, b0, b1);
                }
            }
            float o[2][4];
#pragma unroll
            for (int nt = 0; nt < 2; nt++) {
                int col = wn * 16 + nt * 8 + lr * 2;
                o[nt][0] = oA[nt][0] + oB[nt][0] + sbv[col];
                o[nt][1] = oA[nt][1] + oB[nt][1] + sbv[col + 1];
                o[nt][2] = oA[nt][2] + oB[nt][2] + sbv[col];
                o[nt][3] = oA[nt][3] + oB[nt][3] + sbv[col + 1];
            }
            int r0 = wm * 16 + lq, r1 = r0 + 8;
            float slo = o[0][0] + o[0][1] + o[1][0] + o[1][1];
            float shi = o[0][2] + o[0][3] + o[1][2] + o[1][3];
            float qlo = o[0][0]*o[0][0] + o[0][1]*o[0][1] + o[1][0]*o[1][0] + o[1][1]*o[1][1];
            float qhi = o[0][2]*o[0][2] + o[0][3]*o[0][3] + o[1][2]*o[1][2] + o[1][3]*o[1][3];
#pragma unroll
            for (int off = 1; off <= 2; off <<= 1) {
                slo += __shfl_xor_sync(FULLMASK, slo, off);
                shi += __shfl_xor_sync(FULLMASK, shi, off);
                qlo += __shfl_xor_sync(FULLMASK, qlo, off);
                qhi += __shfl_xor_sync(FULLMASK, qhi, off);
            }
            if (lr == 0) {
                sRedS[r0 * 4 + wn] = slo;  sRedQ[r0 * 4 + wn] = qlo;
                sRedS[r1 * 4 + wn] = shi;  sRedQ[r1 * 4 + wn] = qhi;
            }
            __syncthreads();

            float msl = 0.f, mql = 0.f, msh = 0.f, mqh = 0.f;
#pragma unroll
            for (int j = 0; j < 4; j++) {
                msl += sRedS[r0 * 4 + j];  mql += sRedQ[r0 * 4 + j];
                msh += sRedS[r1 * 4 + j];  mqh += sRedQ[r1 * 4 + j];
            }
            float mean_lo = msl * (1.f / 64.f);
            float mean_hi = msh * (1.f / 64.f);
            float inv_lo = rsqrtf(mql * (1.f / 64.f) - mean_lo * mean_lo + 1e-5f);
            float inv_hi = rsqrtf(mqh * (1.f / 64.f) - mean_hi * mean_hi + 1e-5f);

            size_t gb = ((size_t)b * Nn + n_base) * 64;
#pragma unroll
            for (int nt = 0; nt < 2; nt++) {
                int col = wn * 16 + nt * 8 + lr * 2;
                float ga = sg1[col], gbq = sg1[col + 1];
                float ea = sbe1[col], eb = sbe1[col + 1];
                float2 rlo, rhi;
                rlo.x = (o[nt][0] - mean_lo) * inv_lo * ga  + ea;
                rlo.y = (o[nt][1] - mean_lo) * inv_lo * gbq + eb;
                rhi.x = (o[nt][2] - mean_hi) * inv_hi * ga  + ea;
                rhi.y = (o[nt][3] - mean_hi) * inv_hi * gbq + eb;
                *(float2*)(g_z1 + gb + (size_t)r0 * 64 + col) = rlo;
                *(float2*)(g_z1 + gb + (size_t)r1 * 64 + col) = rhi;
            }
        }
        __syncthreads();
    }
}

// ---------------------------------------------------------------------------
// Kernel B (tf32 tensor cores): MLP + LN2 + shortcut (GEMM2 chain split)
// ---------------------------------------------------------------------------
constexpr int P_WM1 = 264;
constexpr int P_WM2 = 72;
constexpr int P_WS  = 72;
constexpr int P_Z   = 68;
constexpr int P_H   = 260;

extern "C" __global__ void __launch_bounds__(512)
kernelB(const float* __restrict__ x,
        const float* __restrict__ Wm1, const float* __restrict__ bm1,
        const float* __restrict__ Wm2, const float* __restrict__ bm2,
        const float* __restrict__ g2,  const float* __restrict__ be2,
        const float* __restrict__ Ws,  const float* __restrict__ bs,
        float* __restrict__ out)
{
    extern __shared__ float sm[];
    float* sWm1f = sm;
    float* sWm2f = sWm1f + 64 * P_WM1;
    float* sWsf  = sWm2f + 256 * P_WM2;
    float* sbm1  = sWsf + 64 * P_WS;
    float* sbm2  = sbm1 + 256;
    float* sg2   = sbm2 + 64;
    float* sbe2  = sg2 + 64;
    float* sbs   = sbe2 + 64;
    float* sZ    = sbs + 64;
    float* sX    = sZ + 32 * P_Z;
    float* sH    = sX + 32 * P_Z;
    float* sRedS = sH + 32 * P_H;
    float* sRedQ = sRedS + 256;

    int tid = threadIdx.x;
    for (int i = tid; i < 64 * 256; i += 512) {
        int k = i >> 8, n = i & 255;
        sWm1f[k * P_WM1 + n] = to_tf32(Wm1[i]);
    }
    for (int i = tid; i < 256 * 64; i += 512) {
        int k = i >> 6, n = i & 63;
        sWm2f[k * P_WM2 + n] = to_tf32(Wm2[i]);
    }
    for (int i = tid; i < 64 * 64; i += 512) {
        int k = i >> 6, n = i & 63;
        sWsf[k * P_WS + n] = to_tf32(Ws[i]);
    }
    if (tid < 256) sbm1[tid] = bm1[tid];
    if (tid < 64) { sbm2[tid] = bm2[tid]; sg2[tid] = g2[tid]; sbe2[tid] = be2[tid]; sbs[tid] = bs[tid]; }
    __syncthreads();

    const int warp = tid >> 5, lane = tid & 31;
    const int wm = warp >> 3, wn = warp & 7;
    const int lq = lane >> 2, lr = lane & 3;
    const int row_lo = wm * 16 + lq;
    const int row_hi = row_lo + 8;
    const int NTILES = Bb * Nn / 32;

    for (int tile = blockIdx.x; tile < NTILES; tile += gridDim.x) {
        size_t base = (size_t)tile * 32 * 64;
        {
            int row = tid >> 4, seg = (tid & 15) * 4;
            float4 z4 = *(const float4*)(g_z1 + base + row * 64 + seg);
            float4 x4 = *(const float4*)(x + base + row * 64 + seg);
            z4.x = to_tf32(z4.x); z4.y = to_tf32(z4.y); z4.z = to_tf32(z4.z); z4.w = to_tf32(z4.w);
            x4.x = to_tf32(x4.x); x4.y = to_tf32(x4.y); x4.z = to_tf32(x4.z); x4.w = to_tf32(x4.w);
            *(float4*)&sZ[row * P_Z + seg] = z4;
            *(float4*)&sX[row * P_Z + seg] = x4;
        }
        __syncthreads();

        float c[4][4];
#pragma unroll
        for (int nt = 0; nt < 4; nt++)
#pragma unroll
            for (int j = 0; j < 4; j++) c[nt][j] = 0.f;

        const float* A1 = sZ + (wm * 16 + lq) * P_Z + lr;
#pragma unroll
        for (int k0 = 0; k0 < 64; k0 += 8) {
            uint32_t a0 = __float_as_uint(A1[k0]);
            uint32_t a1 = __float_as_uint(A1[k0 + 8 * P_Z]);
            uint32_t a2 = __float_as_uint(A1[k0 + 4]);
            uint32_t a3 = __float_as_uint(A1[k0 + 8 * P_Z + 4]);
            const float* B1 = sWm1f + (k0 + lr) * P_WM1 + wn * 32 + lq;
#pragma unroll
            for (int nt = 0; nt < 4; nt++) {
                uint32_t b0 = __float_as_uint(B1[nt * 8]);
                uint32_t b1 = __float_as_uint(B1[4 * P_WM1 + nt * 8]);
                mma_tf32(c[nt], a0, a1, a2, a3, b0, b1);
            }
        }
#pragma unroll
        for (int nt = 0; nt < 4; nt++) {
            int col = wn * 32 + nt * 8 + lr * 2;
            float v0 = c[nt][0] + sbm1[col];
            float v1 = c[nt][1] + sbm1[col + 1];
            float v2 = c[nt][2] + sbm1[col];
            float v3 = c[nt][3] + sbm1[col + 1];
            sH[row_lo * P_H + col]     = to_tf32(v0 * 0.5f * (1.f + erff(v0 * 0.70710678118654752f)));
            sH[row_lo * P_H + col + 1] = to_tf32(v1 * 0.5f * (1.f + erff(v1 * 0.70710678118654752f)));
            sH[row_hi * P_H + col]     = to_tf32(v2 * 0.5f * (1.f + erff(v2 * 0.70710678118654752f)));
            sH[row_hi * P_H + col + 1] = to_tf32(v3 * 0.5f * (1.f + erff(v3 * 0.70710678118654752f)));
        }
        __syncthreads();

        float oE[4] = {0.f, 0.f, 0.f, 0.f};
        float oO[4] = {0.f, 0.f, 0.f, 0.f};
        float s[4] = {0.f, 0.f, 0.f, 0.f};
        const float* A2 = sH + (wm * 16 + lq) * P_H + lr;
        const float* B2 = sWm2f + lr * P_WM2 + wn * 8 + lq;
#pragma unroll
        for (int k0 = 0; k0 < 256; k0 += 16) {
            {
                uint32_t a0 = __float_as_uint(A2[k0]);
                uint32_t a1 = __float_as_uint(A2[k0 + 8 * P_H]);
                uint32_t a2 = __float_as_uint(A2[k0 + 4]);
                uint32_t a3 = __float_as_uint(A2[k0 + 8 * P_H + 4]);
                uint32_t b0 = __float_as_uint(B2[k0 * P_WM2]);
                uint32_t b1 = __float_as_uint(B2[(k0 + 4) * P_WM2]);
                mma_tf32(oE, a0, a1, a2, a3, b0, b1);
            }
            {
                uint32_t a0 = __float_as_uint(A2[k0 + 8]);
                uint32_t a1 = __float_as_uint(A2[k0 + 8 + 8 * P_H]);
                uint32_t a2 = __float_as_uint(A2[k0 + 8 + 4]);
                uint32_t a3 = __float_as_uint(A2[k0 + 8 + 8 * P_H + 4]);
                uint32_t b0 = __float_as_uint(B2[(k0 + 8) * P_WM2]);
                uint32_t b1 = __float_as_uint(B2[(k0 + 12) * P_WM2]);
                mma_tf32(oO, a0, a1, a2, a3, b0, b1);
            }
        }
        const float* A3 = sX + (wm * 16 + lq) * P_Z + lr;
        const float* B3 = sWsf + lr * P_WS + wn * 8 + lq;
#pragma unroll
        for (int k0 = 0; k0 < 64; k0 += 8) {
            uint32_t a0 = __float_as_uint(A3[k0]);
            uint32_t a1 = __float_as_uint(A3[k0 + 8 * P_Z]);
            uint32_t a2 = __float_as_uint(A3[k0 + 4]);
            uint32_t a3 = __float_as_uint(A3[k0 + 8 * P_Z + 4]);
            uint32_t b0 = __float_as_uint(B3[k0 * P_WS]);
            uint32_t b1 = __float_as_uint(B3[(k0 + 4) * P_WS]);
            mma_tf32(s, a0, a1, a2, a3, b0, b1);
        }

        int col = wn * 8 + lr * 2;
        float o[4];
        o[0] = oE[0] + oO[0] + sbm2[col];
        o[1] = oE[1] + oO[1] + sbm2[col + 1];
        o[2] = oE[2] + oO[2] + sbm2[col];
        o[3] = oE[3] + oO[3] + sbm2[col + 1];

        float slo = o[0] + o[1], shi = o[2] + o[3];
        float qlo = o[0] * o[0] + o[1] * o[1], qhi = o[2] * o[2] + o[3] * o[3];
#pragma unroll
        for (int off = 1; off <= 2; off <<= 1) {
            slo += __shfl_xor_sync(FULLMASK, slo, off);
            shi += __shfl_xor_sync(FULLMASK, shi, off);
            qlo += __shfl_xor_sync(FULLMASK, qlo, off);
            qhi += __shfl_xor_sync(FULLMASK, qhi, off);
        }
        if (lr == 0) {
            sRedS[row_lo * 8 + wn] = slo;  sRedQ[row_lo * 8 + wn] = qlo;
            sRedS[row_hi * 8 + wn] = shi;  sRedQ[row_hi * 8 + wn] = qhi;
        }
        __syncthreads();

        float ms_lo = 0.f, mq_lo = 0.f, ms_hi = 0.f, mq_hi = 0.f;
#pragma unroll
        for (int j = 0; j < 8; j++) {
            ms_lo += sRedS[row_lo * 8 + j];  mq_lo += sRedQ[row_lo * 8 + j];
            ms_hi += sRedS[row_hi * 8 + j];  mq_hi += sRedQ[row_hi * 8 + j];
        }
        float mean_lo = ms_lo * (1.f / 64.f);
        float mean_hi = ms_hi * (1.f / 64.f);
        float inv_lo = rsqrtf(mq_lo * (1.f / 64.f) - mean_lo * mean_lo + 1e-5f);
        float inv_hi = rsqrtf(mq_hi * (1.f / 64.f) - mean_hi * mean_hi + 1e-5f);

        float g0 = sg2[col], g1v = sg2[col + 1];
        float e0 = sbe2[col], e1 = sbe2[col + 1];
        float bs0 = sbs[col], bs1 = sbs[col + 1];

        float2 r_lo, r_hi;
        r_lo.x = (o[0] - mean_lo) * inv_lo * g0  + e0 + s[0] + bs0;
        r_lo.y = (o[1] - mean_lo) * inv_lo * g1v + e1 + s[1] + bs1;
        r_hi.x = (o[2] - mean_hi) * inv_hi * g0  + e0 + s[2] + bs0;
        r_hi.y = (o[3] - mean_hi) * inv_hi * g1v + e1 + s[3] + bs1;

        *(float2*)(out + base + (size_t)row_lo * 64 + col) = r_lo;
        *(float2*)(out + base + (size_t)row_hi * 64 + col) = r_hi;
        __syncthreads();
    }
}

// ---------------------------------------------------------------------------
extern "C" void kernel_launch(void* const* d_in, const int* in_sizes, int n_in,
                              void* d_out, int out_size)
{
    const float* u   = (const float*)d_in[0];
    const float* x   = (const float*)d_in[1];
    const float* Wk  = (const float*)d_in[2];
    const float* bk  = (const float*)d_in[3];
    const float* Wq  = (const float*)d_in[4];
    const float* bq  = (const float*)d_in[5];
    const float* Wv  = (const float*)d_in[6];
    const float* bv  = (const float*)d_in[7];
    const float* g1  = (const float*)d_in[8];
    const float* be1 = (const float*)d_in[9];
    const float* Wm1 = (const float*)d_in[10];
    const float* bm1 = (const float*)d_in[11];
    const float* Wm2 = (const float*)d_in[12];
    const float* bm2 = (const float*)d_in[13];
    const float* g2  = (const float*)d_in[14];
    const float* be2 = (const float*)d_in[15];
    const float* Ws  = (const float*)d_in[16];
    const float* bs  = (const float*)d_in[17];
    float* out = (float*)d_out;

    const int smemA = (264 + 3 * 64 + 2176 + 8480 + 512 + 256) * 4;   // 47520 B
    const int smemB = (64 * P_WM1 + 256 * P_WM2 + 64 * P_WS + 256 + 4 * 64 +
                       2 * 32 * P_Z + 32 * P_H + 512) * 4;

    cudaFuncSetAttribute(kernelA, cudaFuncAttributeMaxDynamicSharedMemorySize, smemA);
    cudaFuncSetAttribute(kernelB, cudaFuncAttributeMaxDynamicSharedMemorySize, smemB);

    kernelM<<<140, 256>>>(Wk, bk, Wq, bq, Wv);
    kernelA<<<444, 256, smemA>>>(u, x, bv, g1, be1);
    kernelB<<<148, 512, smemB>>>(x, Wm1, bm1, Wm2, bm2, g2, be2, Ws, bs, out);
}